// round 3
// baseline (speedup 1.0000x reference)
#include <cuda_runtime.h>
#include <math.h>
#include <stdint.h>

#define TT 512
#define BB 64
#define HH 1024
#define G3 3072   // 3*H
#define LL 2
#define NBLOCKS 128   // 32 j-tiles x 4 b-groups, must all be co-resident

// ---------------- scratch (static device arrays; no cudaMalloc) -------------
__device__ float g_xg[(size_t)TT * BB * G3];   // input gates for current layer
__device__ float g_y1[(size_t)TT * BB * HH];   // layer-1 output sequence
__device__ float g_h[2][BB * HH];              // ping-pong hidden state
__device__ float g_wt[(size_t)G3 * HH];        // transposed Whh: [g][k][j]

// grid-barrier state (persists across launches; gen is relative)
__device__ unsigned g_bar_count = 0;
__device__ unsigned g_bar_gen   = 0;

// ---------------- Whh transpose: W[g*H + j][k] -> Wt[g][k][j] ----------------
__global__ void transpose_whh_kernel(const float* __restrict__ W,
                                     float* __restrict__ Wt)
{
    __shared__ float tile[32][33];
    const int g  = blockIdx.z;
    const int j0 = blockIdx.x * 32;
    const int k0 = blockIdx.y * 32;
    const int tx = threadIdx.x;   // 0..31
    const int ty = threadIdx.y;   // 0..7
#pragma unroll
    for (int r = 0; r < 32; r += 8)
        tile[ty + r][tx] = W[(size_t)(g * HH + j0 + ty + r) * HH + k0 + tx];
    __syncthreads();
#pragma unroll
    for (int r = 0; r < 32; r += 8)
        Wt[(size_t)g * HH * HH + (size_t)(k0 + ty + r) * HH + j0 + tx] = tile[tx][ty + r];
}

// ---------------- input projection GEMM --------------------------------------
// C[m,g] = sum_k X[m,k] * W[g,k] + bias[g];  M=T*B, N=3H, K=H
__global__ void gemm_xg_kernel(const float* __restrict__ X,
                               const float* __restrict__ W,
                               const float* __restrict__ bias,
                               float* __restrict__ C)
{
    __shared__ float Xs[16][68];
    __shared__ float Ws[16][132];

    const int m0 = blockIdx.y * 64;
    const int n0 = blockIdx.x * 128;
    const int tid = threadIdx.x;
    const int tm = tid >> 4;
    const int tn = tid & 15;

    float acc[4][8];
#pragma unroll
    for (int i = 0; i < 4; i++)
#pragma unroll
        for (int j = 0; j < 8; j++) acc[i][j] = 0.f;

    for (int kt = 0; kt < HH; kt += 16) {
        {
            int m = tid >> 2, kq = tid & 3;
            float4 v = *(const float4*)&X[(size_t)(m0 + m) * HH + kt + kq * 4];
            Xs[kq * 4 + 0][m] = v.x;
            Xs[kq * 4 + 1][m] = v.y;
            Xs[kq * 4 + 2][m] = v.z;
            Xs[kq * 4 + 3][m] = v.w;
        }
#pragma unroll
        for (int it = 0; it < 2; it++) {
            int t2 = tid + it * 256;
            int gg = t2 >> 2, kq = t2 & 3;
            float4 v = *(const float4*)&W[(size_t)(n0 + gg) * HH + kt + kq * 4];
            Ws[kq * 4 + 0][gg] = v.x;
            Ws[kq * 4 + 1][gg] = v.y;
            Ws[kq * 4 + 2][gg] = v.z;
            Ws[kq * 4 + 3][gg] = v.w;
        }
        __syncthreads();

#pragma unroll
        for (int k = 0; k < 16; k++) {
            float4 a  = *(const float4*)&Xs[k][tm * 4];
            float4 b0 = *(const float4*)&Ws[k][tn * 8];
            float4 b1 = *(const float4*)&Ws[k][tn * 8 + 4];
            float av[4] = {a.x, a.y, a.z, a.w};
            float bv[8] = {b0.x, b0.y, b0.z, b0.w, b1.x, b1.y, b1.z, b1.w};
#pragma unroll
            for (int i = 0; i < 4; i++)
#pragma unroll
                for (int j = 0; j < 8; j++) acc[i][j] = fmaf(av[i], bv[j], acc[i][j]);
        }
        __syncthreads();
    }

#pragma unroll
    for (int i = 0; i < 4; i++) {
        int m = m0 + tm * 4 + i;
        size_t base = (size_t)m * G3 + n0 + tn * 8;
#pragma unroll
        for (int j = 0; j < 8; j++)
            C[base + j] = acc[i][j] + bias[n0 + tn * 8 + j];
    }
}

// ---------------- software grid barrier --------------------------------------
__device__ __forceinline__ void grid_bar()
{
    __threadfence();          // every thread publishes its writes
    __syncthreads();
    if (threadIdx.x == 0) {
        unsigned gen = *(volatile unsigned*)&g_bar_gen;  // read BEFORE arriving
        if (atomicAdd(&g_bar_count, 1u) == NBLOCKS - 1) {
            g_bar_count = 0;
            __threadfence();
            *(volatile unsigned*)&g_bar_gen = gen + 1;   // release
        } else {
            while (*(volatile unsigned*)&g_bar_gen == gen) __nanosleep(64);
        }
        __threadfence();
    }
    __syncthreads();
}

// ---------------- persistent GRU layer ----------------------------------------
// grid (32, 4): jt = blockIdx.x (32 j per tile), b0 = blockIdx.y*16.
// 128 threads = 4 warps; lane -> j; warps split K (256 k each), block-reduce.
__global__ void __launch_bounds__(128, 1)
gru_layer_persistent(const float* __restrict__ h0,    // [B,H] this layer
                     const float* __restrict__ Wt,    // [3][H(k)][H(j)]
                     const float* __restrict__ bhh,   // [3H]
                     const float* __restrict__ xg,    // [T,B,3H]
                     float* __restrict__ Y,           // [T,B,H]
                     float* __restrict__ hn,          // [B,H] or null
                     float* __restrict__ hb0,
                     float* __restrict__ hb1)
{
    extern __shared__ float hs[];                 // [16][1024] = 64 KB
    __shared__ float red[4][3][16][32];           // 24 KB

    const int tid  = threadIdx.x;
    const int lane = tid & 31;
    const int w    = tid >> 5;
    const int jt   = blockIdx.x;
    const int b0   = blockIdx.y * 16;
    const int j    = jt * 32 + lane;
    const int k0   = w * 256;

    const float br = bhh[j];
    const float bz = bhh[HH + j];
    const float bn = bhh[2 * HH + j];

    const float* wbase = Wt + (size_t)k0 * HH + j;

    for (int t = 0; t < TT; ++t) {
        // ---- stage h(t) for our 16 batches into smem (bypass L1: ping-pong reuse) ----
        const float* hsrc = (t == 0) ? (h0 + (size_t)b0 * HH)
                                     : (((t & 1) ? hb1 : hb0) + (size_t)b0 * HH);
        for (int i = tid; i < 16 * 256; i += 128) {
            int bb = i >> 8, q = i & 255;
            float4 v = __ldcv((const float4*)(hsrc + (size_t)bb * HH) + q);
            *(float4*)&hs[bb * 1024 + q * 4] = v;
        }
        __syncthreads();

        // ---- partial dot products over this warp's k range ----
        float acc[3][16];
#pragma unroll
        for (int g = 0; g < 3; g++)
#pragma unroll
            for (int bb = 0; bb < 16; bb++) acc[g][bb] = 0.f;

        float wreg[2][3][4];
#pragma unroll
        for (int g = 0; g < 3; g++)
#pragma unroll
            for (int kk = 0; kk < 4; kk++)
                wreg[0][g][kk] = __ldg(wbase + (size_t)g * HH * HH + (size_t)kk * HH);

        for (int kc = 0; kc < 256; kc += 4) {
            const int cur = (kc >> 2) & 1;
            const int nxt = cur ^ 1;
            if (kc + 4 < 256) {
#pragma unroll
                for (int g = 0; g < 3; g++)
#pragma unroll
                    for (int kk = 0; kk < 4; kk++)
                        wreg[nxt][g][kk] =
                            __ldg(wbase + (size_t)g * HH * HH + (size_t)(kc + 4 + kk) * HH);
            }
#pragma unroll
            for (int bb = 0; bb < 16; bb++) {
                float4 hv = *(const float4*)&hs[bb * 1024 + k0 + kc];  // uniform broadcast
                acc[0][bb] = fmaf(wreg[cur][0][0], hv.x, acc[0][bb]);
                acc[0][bb] = fmaf(wreg[cur][0][1], hv.y, acc[0][bb]);
                acc[0][bb] = fmaf(wreg[cur][0][2], hv.z, acc[0][bb]);
                acc[0][bb] = fmaf(wreg[cur][0][3], hv.w, acc[0][bb]);
                acc[1][bb] = fmaf(wreg[cur][1][0], hv.x, acc[1][bb]);
                acc[1][bb] = fmaf(wreg[cur][1][1], hv.y, acc[1][bb]);
                acc[1][bb] = fmaf(wreg[cur][1][2], hv.z, acc[1][bb]);
                acc[1][bb] = fmaf(wreg[cur][1][3], hv.w, acc[1][bb]);
                acc[2][bb] = fmaf(wreg[cur][2][0], hv.x, acc[2][bb]);
                acc[2][bb] = fmaf(wreg[cur][2][1], hv.y, acc[2][bb]);
                acc[2][bb] = fmaf(wreg[cur][2][2], hv.z, acc[2][bb]);
                acc[2][bb] = fmaf(wreg[cur][2][3], hv.w, acc[2][bb]);
            }
        }

        // ---- cross-warp reduction ----
#pragma unroll
        for (int g = 0; g < 3; g++)
#pragma unroll
            for (int bb = 0; bb < 16; bb++)
                red[w][g][bb][lane] = acc[g][bb];
        __syncthreads();

        // ---- gate math + state update: each thread owns 4 (b, j) outputs ----
        float* hdst = (t & 1) ? hb0 : hb1;   // buffer (t+1)&1
#pragma unroll
        for (int i = 0; i < 4; i++) {
            int bb = w * 4 + i;
            float s0 = 0.f, s1 = 0.f, s2 = 0.f;
#pragma unroll
            for (int wp = 0; wp < 4; wp++) {
                s0 += red[wp][0][bb][lane];
                s1 += red[wp][1][bb][lane];
                s2 += red[wp][2][bb][lane];
            }
            int b = b0 + bb;
            const float* xrow = xg + ((size_t)t * BB + b) * G3;
            float r = 1.f / (1.f + expf(-(xrow[j] + s0 + br)));
            float z = 1.f / (1.f + expf(-(xrow[HH + j] + s1 + bz)));
            float n = tanhf(xrow[2 * HH + j] + r * (s2 + bn));
            float hp = hs[bb * 1024 + j];
            float hv = (1.f - z) * n + z * hp;
            hdst[(size_t)b * HH + j] = hv;
            Y[((size_t)t * BB + b) * HH + j] = hv;
            if (hn != nullptr && t == TT - 1) hn[(size_t)b * HH + j] = hv;
        }

        grid_bar();   // h(t+1) globally visible before next staging
    }
}

// ---------------- launch -------------------------------------------------------
extern "C" void kernel_launch(void* const* d_in, const int* in_sizes, int n_in,
                              void* d_out, int out_size)
{
    const float* x   = (const float*)d_in[0];   // [T,B,H]
    const float* h0  = (const float*)d_in[1];   // [L,B,H]
    const float* Wih = (const float*)d_in[2];   // [L,3H,H]
    const float* Whh = (const float*)d_in[3];   // [L,3H,H]
    const float* bih = (const float*)d_in[4];   // [L,3H]
    const float* bhh = (const float*)d_in[5];   // [L,3H]
    float* out = (float*)d_out;                 // [T,B,H] (+ [L,B,H] h_n)

    float *xg = nullptr, *y1 = nullptr, *hb = nullptr, *wt = nullptr;
    cudaGetSymbolAddress((void**)&xg, g_xg);
    cudaGetSymbolAddress((void**)&y1, g_y1);
    cudaGetSymbolAddress((void**)&hb, g_h);
    cudaGetSymbolAddress((void**)&wt, g_wt);

    static bool attr_set = false;
    if (!attr_set) {
        cudaFuncSetAttribute(gru_layer_persistent,
                             cudaFuncAttributeMaxDynamicSharedMemorySize,
                             16 * 1024 * 4);
        attr_set = true;
    }

    const dim3 gemmGrid(G3 / 128, (TT * BB) / 64);
    const dim3 trGrid(HH / 32, HH / 32, 3);
    const dim3 stepGrid(32, 4);
    const bool write_hn = (out_size >= TT * BB * HH + LL * BB * HH);

    for (int l = 0; l < LL; l++) {
        const float* Xin = (l == 0) ? x : y1;
        float* Y         = (l == 0) ? y1 : out;
        float* hn        = write_hn
            ? out + (size_t)TT * BB * HH + (size_t)l * BB * HH : nullptr;

        transpose_whh_kernel<<<trGrid, dim3(32, 8)>>>(
            Whh + (size_t)l * G3 * HH, wt);

        gemm_xg_kernel<<<gemmGrid, 256>>>(
            Xin, Wih + (size_t)l * G3 * HH, bih + (size_t)l * G3, xg);

        gru_layer_persistent<<<stepGrid, 128, 16 * 1024 * 4>>>(
            h0 + (size_t)l * BB * HH, wt, bhh + (size_t)l * G3,
            xg, Y, hn, hb, hb + BB * HH);
    }
}

// round 6
// speedup vs baseline: 1.5606x; 1.5606x over previous
#include <cuda_runtime.h>
#include <cuda_bf16.h>
#include <math.h>
#include <stdint.h>

#define TT 512
#define BB 64
#define HH 1024
#define G3 3072   // 3*H
#define LL 2
#define NBLOCKS 128   // persistent grid: 32 j-tiles x 4 b-groups

// ---------------- scratch (static device arrays; no cudaMalloc) -------------
__device__ float g_xg[(size_t)TT * BB * G3];          // input gates, current layer
__device__ float g_y1[(size_t)TT * BB * HH];          // layer-1 output sequence
__device__ float g_h[2][BB * HH];                     // ping-pong hidden state
__device__ float g_wt[(size_t)G3 * HH];               // transposed Whh: [g][k][j]
__device__ __nv_bfloat16 g_xhi[(size_t)TT * BB * HH]; // split X (hi)
__device__ __nv_bfloat16 g_xlo[(size_t)TT * BB * HH]; // split X (lo)
__device__ __nv_bfloat16 g_whi[(size_t)G3 * HH];      // split Wih (hi)
__device__ __nv_bfloat16 g_wlo[(size_t)G3 * HH];      // split Wih (lo)

// grid-barrier state
__device__ unsigned g_bar_count = 0;
__device__ unsigned g_bar_gen   = 0;

// ======================= warp MMA helpers (sm_80+ PTX, valid on compute_103) ==
__device__ __forceinline__ uint32_t smem_u32(const void* p) {
    uint32_t a;
    asm("{ .reg .u64 t; cvta.to.shared.u64 t, %1; cvt.u32.u64 %0, t; }"
        : "=r"(a) : "l"(p));
    return a;
}
__device__ __forceinline__ void ldmx4(uint32_t* r, uint32_t addr) {
    asm volatile("ldmatrix.sync.aligned.m8n8.x4.shared.b16 {%0,%1,%2,%3}, [%4];"
        : "=r"(r[0]), "=r"(r[1]), "=r"(r[2]), "=r"(r[3]) : "r"(addr));
}
__device__ __forceinline__ void mma16816(float* c, const uint32_t* a, const uint32_t* b) {
    asm volatile("mma.sync.aligned.m16n8k16.row.col.f32.bf16.bf16.f32 "
        "{%0,%1,%2,%3}, {%4,%5,%6,%7}, {%8,%9}, {%0,%1,%2,%3};"
        : "+f"(c[0]), "+f"(c[1]), "+f"(c[2]), "+f"(c[3])
        : "r"(a[0]), "r"(a[1]), "r"(a[2]), "r"(a[3]), "r"(b[0]), "r"(b[1]));
}

// ---------------- fp32 -> (hi, lo) bf16 split --------------------------------
__global__ void split_f32_kernel(const float* __restrict__ src,
                                 __nv_bfloat16* __restrict__ hi,
                                 __nv_bfloat16* __restrict__ lo, int n4)
{
    int i = blockIdx.x * blockDim.x + threadIdx.x;
    if (i >= n4) return;
    float4 v = ((const float4*)src)[i];
    float f[4] = {v.x, v.y, v.z, v.w};
    uint32_t ph[2], pl[2];
#pragma unroll
    for (int q = 0; q < 2; q++) {
        __nv_bfloat16 h0 = __float2bfloat16(f[q * 2 + 0]);
        __nv_bfloat16 h1 = __float2bfloat16(f[q * 2 + 1]);
        __nv_bfloat16 l0 = __float2bfloat16(f[q * 2 + 0] - __bfloat162float(h0));
        __nv_bfloat16 l1 = __float2bfloat16(f[q * 2 + 1] - __bfloat162float(h1));
        ph[q] = (uint32_t)__bfloat16_as_ushort(h0) | ((uint32_t)__bfloat16_as_ushort(h1) << 16);
        pl[q] = (uint32_t)__bfloat16_as_ushort(l0) | ((uint32_t)__bfloat16_as_ushort(l1) << 16);
    }
    ((uint2*)hi)[i] = make_uint2(ph[0], ph[1]);
    ((uint2*)lo)[i] = make_uint2(pl[0], pl[1]);
}

// ---------------- Whh transpose: W[g*H + j][k] -> Wt[g][k][j] ----------------
__global__ void transpose_whh_kernel(const float* __restrict__ W,
                                     float* __restrict__ Wt)
{
    __shared__ float tile[32][33];
    const int g  = blockIdx.z;
    const int j0 = blockIdx.x * 32;
    const int k0 = blockIdx.y * 32;
    const int tx = threadIdx.x;
    const int ty = threadIdx.y;
#pragma unroll
    for (int r = 0; r < 32; r += 8)
        tile[ty + r][tx] = W[(size_t)(g * HH + j0 + ty + r) * HH + k0 + tx];
    __syncthreads();
#pragma unroll
    for (int r = 0; r < 32; r += 8)
        Wt[(size_t)g * HH * HH + (size_t)(k0 + ty + r) * HH + j0 + tx] = tile[tx][ty + r];
}

// ---------------- HMMA bf16-split input GEMM ----------------------------------
// C[m,n] = sum_k X[m,k] * W[n,k] + bias[n]
// CTA 128(m) x 128(n), 256 threads = 8 warps in 2(m) x 4(n); warp tile 64x32.
// K chunk 64; smem tiles padded to 72 bf16 (144B) rows -> conflict-free ldmatrix.
// B tiles are stored [n][k] row-major: that IS the .col B fragment layout, so
// B uses NON-trans ldmatrix (the round-5 bug was using .trans here).
#define SROW 72
__global__ void __launch_bounds__(256, 1)
gemm_xg_hmma(const __nv_bfloat16* __restrict__ Xhi, const __nv_bfloat16* __restrict__ Xlo,
             const __nv_bfloat16* __restrict__ Whi, const __nv_bfloat16* __restrict__ Wlo,
             const float* __restrict__ bias, float* __restrict__ C)
{
    extern __shared__ __nv_bfloat16 sm[];   // 4 tiles x [128][72]
    const int TILE = 128 * SROW;            // elements per tile

    const int tid  = threadIdx.x;
    const int lane = tid & 31;
    const int wid  = tid >> 5;
    const int wm   = wid & 1;               // 0..1  (m 64-tile)
    const int wn   = wid >> 1;              // 0..3  (n 32-tile)
    const int n0   = blockIdx.x * 128;
    const int m0   = blockIdx.y * 128;

    const uint32_t smb = smem_u32(sm);

    float acc[4][4][4];
#pragma unroll
    for (int i = 0; i < 4; i++)
#pragma unroll
        for (int j = 0; j < 4; j++)
#pragma unroll
            for (int q = 0; q < 4; q++) acc[i][j][q] = 0.f;

    // ldmatrix base offsets (element units)
    // A: lanes 0-15 -> rows m0-15 (k cols 0-7), lanes 16-31 -> same rows, k cols 8-15
    const int arow = (wm * 64 + (lane & 15)) * SROW + (lane >> 4) * 8;
    // B ([n][k] rows): lanes 0-7: n0-7/k0; 8-15: n0-7/k8; 16-23: n8-15/k0; 24-31: n8-15/k8
    const int brow = (wn * 32 + (lane & 7) + ((lane >> 4) << 3)) * SROW
                   + ((lane >> 3) & 1) * 8;

    const __nv_bfloat16* srcs[4] = {
        Xhi + (size_t)m0 * HH, Xlo + (size_t)m0 * HH,
        Whi + (size_t)n0 * HH, Wlo + (size_t)n0 * HH };

    for (int ch = 0; ch < 16; ch++) {
        const int kt = ch * 64;
        // ---- load 4 tiles: 128 rows x 64 bf16 each ----
#pragma unroll
        for (int tile = 0; tile < 4; tile++) {
            const __nv_bfloat16* src = srcs[tile] + kt;
#pragma unroll
            for (int it = 0; it < 4; it++) {
                int idx = tid + it * 256;        // 0..1023
                int row = idx >> 3, c8 = idx & 7;
                float4 v = *(const float4*)(src + (size_t)row * HH + c8 * 8);
                *(float4*)(sm + tile * TILE + row * SROW + c8 * 8) = v;
            }
        }
        __syncthreads();

        // ---- 4 k16 steps ----
#pragma unroll
        for (int ks = 0; ks < 4; ks++) {
            uint32_t ahi[4][4], alo[4][4], bhi[4][2], blo[4][2];
#pragma unroll
            for (int mf = 0; mf < 4; mf++) {
                uint32_t aoff = (uint32_t)(arow + mf * 16 * SROW + ks * 16) * 2;
                ldmx4(ahi[mf], smb + 0 * TILE * 2 + aoff);
                ldmx4(alo[mf], smb + 1 * TILE * 2 + aoff);
            }
#pragma unroll
            for (int pr = 0; pr < 2; pr++) {
                uint32_t boff = (uint32_t)(brow + pr * 16 * SROW + ks * 16) * 2;
                uint32_t rh[4], rl[4];
                ldmx4(rh, smb + 2 * TILE * 2 + boff);   // NON-trans (fix)
                ldmx4(rl, smb + 3 * TILE * 2 + boff);   // NON-trans (fix)
                bhi[pr * 2 + 0][0] = rh[0]; bhi[pr * 2 + 0][1] = rh[1];
                bhi[pr * 2 + 1][0] = rh[2]; bhi[pr * 2 + 1][1] = rh[3];
                blo[pr * 2 + 0][0] = rl[0]; blo[pr * 2 + 0][1] = rl[1];
                blo[pr * 2 + 1][0] = rl[2]; blo[pr * 2 + 1][1] = rl[3];
            }
#pragma unroll
            for (int mf = 0; mf < 4; mf++)
#pragma unroll
                for (int nf = 0; nf < 4; nf++) {
                    mma16816(acc[mf][nf], ahi[mf], bhi[nf]);
                    mma16816(acc[mf][nf], ahi[mf], blo[nf]);
                    mma16816(acc[mf][nf], alo[mf], bhi[nf]);
                }
        }
        __syncthreads();
    }

    // ---- epilogue: direct STG (float2 pairs) + bias ----
#pragma unroll
    for (int mf = 0; mf < 4; mf++) {
        int row = m0 + wm * 64 + mf * 16 + (lane >> 2);
#pragma unroll
        for (int nf = 0; nf < 4; nf++) {
            int col = n0 + wn * 32 + nf * 8 + (lane & 3) * 2;
            float b0 = bias[col], b1 = bias[col + 1];
            float2 v0 = make_float2(acc[mf][nf][0] + b0, acc[mf][nf][1] + b1);
            float2 v1 = make_float2(acc[mf][nf][2] + b0, acc[mf][nf][3] + b1);
            *(float2*)&C[(size_t)row * G3 + col]       = v0;
            *(float2*)&C[(size_t)(row + 8) * G3 + col] = v1;
        }
    }
}

// ---------------- software grid barrier --------------------------------------
__device__ __forceinline__ void grid_bar()
{
    __threadfence();
    __syncthreads();
    if (threadIdx.x == 0) {
        unsigned gen = *(volatile unsigned*)&g_bar_gen;
        if (atomicAdd(&g_bar_count, 1u) == NBLOCKS - 1) {
            g_bar_count = 0;
            __threadfence();
            *(volatile unsigned*)&g_bar_gen = gen + 1;
        } else {
            while (*(volatile unsigned*)&g_bar_gen == gen) __nanosleep(64);
        }
        __threadfence();
    }
    __syncthreads();
}

// ---------------- persistent GRU layer (8 warps, k-split 8) -------------------
__global__ void __launch_bounds__(256, 1)
gru_layer_persistent(const float* __restrict__ h0,
                     const float* __restrict__ Wt,    // [3][H(k)][H(j)]
                     const float* __restrict__ bhh,
                     const float* __restrict__ xg,    // [T,B,3H]
                     float* __restrict__ Y,           // [T,B,H]
                     float* __restrict__ hn,
                     float* __restrict__ hb0,
                     float* __restrict__ hb1)
{
    extern __shared__ float hs[];                // [16][1024] = 64 KB
    float* red = hs + 16 * 1024;                 // [8][3][16][32] = 48 KB

    const int tid  = threadIdx.x;
    const int lane = tid & 31;
    const int w    = tid >> 5;                   // 0..7
    const int jt   = blockIdx.x;
    const int b0   = blockIdx.y * 16;
    const int j    = jt * 32 + lane;
    const int k0   = w * 128;

    const float br = bhh[j];
    const float bz = bhh[HH + j];
    const float bn = bhh[2 * HH + j];
    const float* wbase = Wt + (size_t)k0 * HH + j;

    for (int t = 0; t < TT; ++t) {
        const float* hsrc = (t == 0) ? (h0 + (size_t)b0 * HH)
                                     : (((t & 1) ? hb1 : hb0) + (size_t)b0 * HH);
        for (int i = tid; i < 16 * 256; i += 256) {
            int bb = i >> 8, q = i & 255;
            float4 v = __ldcv((const float4*)(hsrc + (size_t)bb * HH) + q);
            *(float4*)&hs[bb * 1024 + q * 4] = v;
        }
        __syncthreads();

        float acc[3][16];
#pragma unroll
        for (int g = 0; g < 3; g++)
#pragma unroll
            for (int bb = 0; bb < 16; bb++) acc[g][bb] = 0.f;

        float wreg[2][3][4];
#pragma unroll
        for (int g = 0; g < 3; g++)
#pragma unroll
            for (int kk = 0; kk < 4; kk++)
                wreg[0][g][kk] = __ldg(wbase + (size_t)g * HH * HH + (size_t)kk * HH);

        for (int kc = 0; kc < 128; kc += 4) {
            const int cur = (kc >> 2) & 1;
            const int nxt = cur ^ 1;
            if (kc + 4 < 128) {
#pragma unroll
                for (int g = 0; g < 3; g++)
#pragma unroll
                    for (int kk = 0; kk < 4; kk++)
                        wreg[nxt][g][kk] =
                            __ldg(wbase + (size_t)g * HH * HH + (size_t)(kc + 4 + kk) * HH);
            }
#pragma unroll
            for (int bb = 0; bb < 16; bb++) {
                float4 hv = *(const float4*)&hs[bb * 1024 + k0 + kc];
                acc[0][bb] = fmaf(wreg[cur][0][0], hv.x, acc[0][bb]);
                acc[0][bb] = fmaf(wreg[cur][0][1], hv.y, acc[0][bb]);
                acc[0][bb] = fmaf(wreg[cur][0][2], hv.z, acc[0][bb]);
                acc[0][bb] = fmaf(wreg[cur][0][3], hv.w, acc[0][bb]);
                acc[1][bb] = fmaf(wreg[cur][1][0], hv.x, acc[1][bb]);
                acc[1][bb] = fmaf(wreg[cur][1][1], hv.y, acc[1][bb]);
                acc[1][bb] = fmaf(wreg[cur][1][2], hv.z, acc[1][bb]);
                acc[1][bb] = fmaf(wreg[cur][1][3], hv.w, acc[1][bb]);
                acc[2][bb] = fmaf(wreg[cur][2][0], hv.x, acc[2][bb]);
                acc[2][bb] = fmaf(wreg[cur][2][1], hv.y, acc[2][bb]);
                acc[2][bb] = fmaf(wreg[cur][2][2], hv.z, acc[2][bb]);
                acc[2][bb] = fmaf(wreg[cur][2][3], hv.w, acc[2][bb]);
            }
        }

#pragma unroll
        for (int g = 0; g < 3; g++)
#pragma unroll
            for (int bb = 0; bb < 16; bb++)
                red[((w * 3 + g) * 16 + bb) * 32 + lane] = acc[g][bb];
        __syncthreads();

        float* hdst = (t & 1) ? hb0 : hb1;
#pragma unroll
        for (int half = 0; half < 2; half++) {
            int bb = w + half * 8;
            float s0 = 0.f, s1 = 0.f, s2 = 0.f;
#pragma unroll
            for (int wp = 0; wp < 8; wp++) {
                s0 += red[((wp * 3 + 0) * 16 + bb) * 32 + lane];
                s1 += red[((wp * 3 + 1) * 16 + bb) * 32 + lane];
                s2 += red[((wp * 3 + 2) * 16 + bb) * 32 + lane];
            }
            int b = b0 + bb;
            const float* xrow = xg + ((size_t)t * BB + b) * G3;
            float r = 1.f / (1.f + expf(-(xrow[j] + s0 + br)));
            float z = 1.f / (1.f + expf(-(xrow[HH + j] + s1 + bz)));
            float n = tanhf(xrow[2 * HH + j] + r * (s2 + bn));
            float hp = hs[bb * 1024 + j];
            float hv = (1.f - z) * n + z * hp;
            hdst[(size_t)b * HH + j] = hv;
            Y[((size_t)t * BB + b) * HH + j] = hv;
            if (hn != nullptr && t == TT - 1) hn[(size_t)b * HH + j] = hv;
        }

        grid_bar();
    }
}

// ---------------- launch -------------------------------------------------------
extern "C" void kernel_launch(void* const* d_in, const int* in_sizes, int n_in,
                              void* d_out, int out_size)
{
    const float* x   = (const float*)d_in[0];
    const float* h0  = (const float*)d_in[1];
    const float* Wih = (const float*)d_in[2];
    const float* Whh = (const float*)d_in[3];
    const float* bih = (const float*)d_in[4];
    const float* bhh = (const float*)d_in[5];
    float* out = (float*)d_out;

    float *xg, *y1, *hb, *wt;
    __nv_bfloat16 *xhi, *xlo, *whi, *wlo;
    cudaGetSymbolAddress((void**)&xg,  g_xg);
    cudaGetSymbolAddress((void**)&y1,  g_y1);
    cudaGetSymbolAddress((void**)&hb,  g_h);
    cudaGetSymbolAddress((void**)&wt,  g_wt);
    cudaGetSymbolAddress((void**)&xhi, g_xhi);
    cudaGetSymbolAddress((void**)&xlo, g_xlo);
    cudaGetSymbolAddress((void**)&whi, g_whi);
    cudaGetSymbolAddress((void**)&wlo, g_wlo);

    const int gemmSmem = 4 * 128 * SROW * 2;   // 73728 B
    static bool attr_set = false;
    if (!attr_set) {
        cudaFuncSetAttribute(gru_layer_persistent,
                             cudaFuncAttributeMaxDynamicSharedMemorySize, 114688);
        cudaFuncSetAttribute(gemm_xg_hmma,
                             cudaFuncAttributeMaxDynamicSharedMemorySize, gemmSmem);
        attr_set = true;
    }

    const dim3 trGrid(HH / 32, HH / 32, 3);
    const dim3 gemmGrid(G3 / 128, (TT * BB) / 128);   // 24 x 256
    const dim3 stepGrid(32, 4);
    const int  n4x = TT * BB * HH / 4;
    const int  n4w = G3 * HH / 4;
    const bool write_hn = (out_size >= TT * BB * HH + LL * BB * HH);

    for (int l = 0; l < LL; l++) {
        const float* Xin = (l == 0) ? x : y1;
        float* Y         = (l == 0) ? y1 : out;
        float* hn        = write_hn
            ? out + (size_t)TT * BB * HH + (size_t)l * BB * HH : nullptr;

        transpose_whh_kernel<<<trGrid, dim3(32, 8)>>>(Whh + (size_t)l * G3 * HH, wt);

        split_f32_kernel<<<(n4x + 255) / 256, 256>>>(Xin, xhi, xlo, n4x);
        split_f32_kernel<<<(n4w + 255) / 256, 256>>>(Wih + (size_t)l * G3 * HH,
                                                     whi, wlo, n4w);

        gemm_xg_hmma<<<gemmGrid, 256, gemmSmem>>>(xhi, xlo, whi, wlo,
                                                  bih + (size_t)l * G3, xg);

        gru_layer_persistent<<<stepGrid, 256, 114688>>>(
            h0 + (size_t)l * BB * HH, wt, bhh + (size_t)l * G3,
            xg, Y, hn, hb, hb + BB * HH);
    }
}

// round 7
// speedup vs baseline: 2.4433x; 1.5657x over previous
#include <cuda_runtime.h>
#include <cuda_bf16.h>
#include <math.h>
#include <stdint.h>

#define TT 512
#define BB 64
#define HH 1024
#define G3 3072   // 3*H
#define LL 2
#define RB 96          // recurrence blocks (persistent, 1/SM, 96 <= 148)
#define WSTRIDE 1032   // W smem row stride (bf16 elements): 2064B, +16B/row shift -> conflict-free
#define HSTRIDE 136    // h tile row stride (bf16 elements): 272B

// ---------------- scratch (static device arrays; no cudaMalloc) -------------
__device__ float g_xg[(size_t)TT * BB * G3];          // input gates, current layer
__device__ float g_y1[(size_t)TT * BB * HH];          // layer-1 output sequence
__device__ __nv_bfloat16 g_xhi[(size_t)TT * BB * HH]; // split X (hi)
__device__ __nv_bfloat16 g_xlo[(size_t)TT * BB * HH]; // split X (lo)
__device__ __nv_bfloat16 g_whi[(size_t)G3 * HH];      // split Wih (hi)
__device__ __nv_bfloat16 g_wlo[(size_t)G3 * HH];      // split Wih (lo)
__device__ __nv_bfloat16 g_vhi[(size_t)G3 * HH];      // split Whh (hi)
__device__ __nv_bfloat16 g_vlo[(size_t)G3 * HH];      // split Whh (lo)
__device__ float g_hf[BB * HH];                       // fp32 master hidden state
__device__ __nv_bfloat16 g_hbh[BB * HH];              // h split hi  [b][k]
__device__ __nv_bfloat16 g_hbl[BB * HH];              // h split lo  [b][k]
__device__ float g_gates[(size_t)BB * G3];            // gate pre-activations [b][3H]

// grid-barrier state
__device__ unsigned g_bar_count = 0;
__device__ unsigned g_bar_gen   = 0;

// ======================= warp MMA helpers (sm_80+ PTX, valid on compute_103) ==
__device__ __forceinline__ uint32_t smem_u32(const void* p) {
    uint32_t a;
    asm("{ .reg .u64 t; cvta.to.shared.u64 t, %1; cvt.u32.u64 %0, t; }"
        : "=r"(a) : "l"(p));
    return a;
}
__device__ __forceinline__ void ldmx4(uint32_t* r, uint32_t addr) {
    asm volatile("ldmatrix.sync.aligned.m8n8.x4.shared.b16 {%0,%1,%2,%3}, [%4];"
        : "=r"(r[0]), "=r"(r[1]), "=r"(r[2]), "=r"(r[3]) : "r"(addr));
}
__device__ __forceinline__ void mma16816(float* c, const uint32_t* a, const uint32_t* b) {
    asm volatile("mma.sync.aligned.m16n8k16.row.col.f32.bf16.bf16.f32 "
        "{%0,%1,%2,%3}, {%4,%5,%6,%7}, {%8,%9}, {%0,%1,%2,%3};"
        : "+f"(c[0]), "+f"(c[1]), "+f"(c[2]), "+f"(c[3])
        : "r"(a[0]), "r"(a[1]), "r"(a[2]), "r"(a[3]), "r"(b[0]), "r"(b[1]));
}
#define CP_ASYNC16(dst, src) \
    asm volatile("cp.async.cg.shared.global [%0], [%1], 16;" :: "r"(dst), "l"(src))
#define CP_COMMIT   asm volatile("cp.async.commit_group;" ::: "memory")
#define CP_WAIT1    asm volatile("cp.async.wait_group 1;" ::: "memory")
#define CP_WAIT0    asm volatile("cp.async.wait_group 0;" ::: "memory")

// ---------------- fp32 -> (hi, lo) bf16 split --------------------------------
__global__ void split_f32_kernel(const float* __restrict__ src,
                                 __nv_bfloat16* __restrict__ hi,
                                 __nv_bfloat16* __restrict__ lo, int n4)
{
    int i = blockIdx.x * blockDim.x + threadIdx.x;
    if (i >= n4) return;
    float4 v = ((const float4*)src)[i];
    float f[4] = {v.x, v.y, v.z, v.w};
    uint32_t ph[2], pl[2];
#pragma unroll
    for (int q = 0; q < 2; q++) {
        __nv_bfloat16 h0 = __float2bfloat16(f[q * 2 + 0]);
        __nv_bfloat16 h1 = __float2bfloat16(f[q * 2 + 1]);
        __nv_bfloat16 l0 = __float2bfloat16(f[q * 2 + 0] - __bfloat162float(h0));
        __nv_bfloat16 l1 = __float2bfloat16(f[q * 2 + 1] - __bfloat162float(h1));
        ph[q] = (uint32_t)__bfloat16_as_ushort(h0) | ((uint32_t)__bfloat16_as_ushort(h1) << 16);
        pl[q] = (uint32_t)__bfloat16_as_ushort(l0) | ((uint32_t)__bfloat16_as_ushort(l1) << 16);
    }
    ((uint2*)hi)[i] = make_uint2(ph[0], ph[1]);
    ((uint2*)lo)[i] = make_uint2(pl[0], pl[1]);
}

// ---------------- HMMA bf16-split input GEMM (unchanged from round 6) ---------
#define SROW 72
__global__ void __launch_bounds__(256, 1)
gemm_xg_hmma(const __nv_bfloat16* __restrict__ Xhi, const __nv_bfloat16* __restrict__ Xlo,
             const __nv_bfloat16* __restrict__ Whi, const __nv_bfloat16* __restrict__ Wlo,
             const float* __restrict__ bias, float* __restrict__ C)
{
    extern __shared__ __nv_bfloat16 sm[];
    const int TILE = 128 * SROW;

    const int tid  = threadIdx.x;
    const int lane = tid & 31;
    const int wid  = tid >> 5;
    const int wm   = wid & 1;
    const int wn   = wid >> 1;
    const int n0   = blockIdx.x * 128;
    const int m0   = blockIdx.y * 128;

    const uint32_t smb = smem_u32(sm);

    float acc[4][4][4];
#pragma unroll
    for (int i = 0; i < 4; i++)
#pragma unroll
        for (int j = 0; j < 4; j++)
#pragma unroll
            for (int q = 0; q < 4; q++) acc[i][j][q] = 0.f;

    const int arow = (wm * 64 + (lane & 15)) * SROW + (lane >> 4) * 8;
    const int brow = (wn * 32 + (lane & 7) + ((lane >> 4) << 3)) * SROW
                   + ((lane >> 3) & 1) * 8;

    const __nv_bfloat16* srcs[4] = {
        Xhi + (size_t)m0 * HH, Xlo + (size_t)m0 * HH,
        Whi + (size_t)n0 * HH, Wlo + (size_t)n0 * HH };

    for (int ch = 0; ch < 16; ch++) {
        const int kt = ch * 64;
#pragma unroll
        for (int tile = 0; tile < 4; tile++) {
            const __nv_bfloat16* src = srcs[tile] + kt;
#pragma unroll
            for (int it = 0; it < 4; it++) {
                int idx = tid + it * 256;
                int row = idx >> 3, c8 = idx & 7;
                float4 v = *(const float4*)(src + (size_t)row * HH + c8 * 8);
                *(float4*)(sm + tile * TILE + row * SROW + c8 * 8) = v;
            }
        }
        __syncthreads();

#pragma unroll
        for (int ks = 0; ks < 4; ks++) {
            uint32_t ahi[4][4], alo[4][4], bhi[4][2], blo[4][2];
#pragma unroll
            for (int mf = 0; mf < 4; mf++) {
                uint32_t aoff = (uint32_t)(arow + mf * 16 * SROW + ks * 16) * 2;
                ldmx4(ahi[mf], smb + 0 * TILE * 2 + aoff);
                ldmx4(alo[mf], smb + 1 * TILE * 2 + aoff);
            }
#pragma unroll
            for (int pr = 0; pr < 2; pr++) {
                uint32_t boff = (uint32_t)(brow + pr * 16 * SROW + ks * 16) * 2;
                uint32_t rh[4], rl[4];
                ldmx4(rh, smb + 2 * TILE * 2 + boff);
                ldmx4(rl, smb + 3 * TILE * 2 + boff);
                bhi[pr * 2 + 0][0] = rh[0]; bhi[pr * 2 + 0][1] = rh[1];
                bhi[pr * 2 + 1][0] = rh[2]; bhi[pr * 2 + 1][1] = rh[3];
                blo[pr * 2 + 0][0] = rl[0]; blo[pr * 2 + 0][1] = rl[1];
                blo[pr * 2 + 1][0] = rl[2]; blo[pr * 2 + 1][1] = rl[3];
            }
#pragma unroll
            for (int mf = 0; mf < 4; mf++)
#pragma unroll
                for (int nf = 0; nf < 4; nf++) {
                    mma16816(acc[mf][nf], ahi[mf], bhi[nf]);
                    mma16816(acc[mf][nf], ahi[mf], blo[nf]);
                    mma16816(acc[mf][nf], alo[mf], bhi[nf]);
                }
        }
        __syncthreads();
    }

#pragma unroll
    for (int mf = 0; mf < 4; mf++) {
        int row = m0 + wm * 64 + mf * 16 + (lane >> 2);
#pragma unroll
        for (int nf = 0; nf < 4; nf++) {
            int col = n0 + wn * 32 + nf * 8 + (lane & 3) * 2;
            float b0 = bias[col], b1 = bias[col + 1];
            float2 v0 = make_float2(acc[mf][nf][0] + b0, acc[mf][nf][1] + b1);
            float2 v1 = make_float2(acc[mf][nf][2] + b0, acc[mf][nf][3] + b1);
            *(float2*)&C[(size_t)row * G3 + col]       = v0;
            *(float2*)&C[(size_t)(row + 8) * G3 + col] = v1;
        }
    }
}

// ---------------- software grid barrier (RB blocks) ---------------------------
__device__ __forceinline__ void grid_bar()
{
    __threadfence();
    __syncthreads();
    if (threadIdx.x == 0) {
        unsigned gen = *(volatile unsigned*)&g_bar_gen;
        if (atomicAdd(&g_bar_count, 1u) == RB - 1) {
            g_bar_count = 0;
            __threadfence();
            *(volatile unsigned*)&g_bar_gen = gen + 1;
        } else {
            while (*(volatile unsigned*)&g_bar_gen == gen) __nanosleep(32);
        }
        __threadfence();
    }
    __syncthreads();
}

// ---------------- persistent HMMA GRU recurrence -----------------------------
// smem: Whi[32][1032] (66048B) | Wlo (66048B) | h dbuf: 2 x {hi 17408B, lo 17408B}
// Phase A: gates[b][3H] = Whh_rows(m0..m0+31) @ h  (bf16 split, fp32 accum)
// Phase B: pointwise GRU update; writes hf (fp32), hbh/hbl (bf16 splits), Y.
__global__ void __launch_bounds__(256, 1)
gru_rec_hmma(const float* __restrict__ h0,
             const __nv_bfloat16* __restrict__ vhi,
             const __nv_bfloat16* __restrict__ vlo,
             const float* __restrict__ bhh,
             const float* __restrict__ xg,     // [T,B,3H]
             float* __restrict__ Y,            // [T,B,H]
             float* __restrict__ hn,           // [B,H] or null
             float* __restrict__ hf,
             __nv_bfloat16* __restrict__ hbh,
             __nv_bfloat16* __restrict__ hbl,
             float* __restrict__ gates)
{
    extern __shared__ char smc[];
    __nv_bfloat16* swhi = (__nv_bfloat16*)smc;
    __nv_bfloat16* swlo = (__nv_bfloat16*)(smc + 66048);
    const uint32_t smb   = smem_u32(smc);
    const uint32_t hbase = smb + 132096;

    const int tid  = threadIdx.x;
    const int lane = tid & 31;
    const int w    = tid >> 5;                 // warp 0..7 -> batches w*8..w*8+7
    const int m0   = blockIdx.x * 32;          // W row slice
    const int gid  = blockIdx.x * 256 + tid;

    // ---- preload this block's Whh slice (both splits) into smem, once ----
    for (int i = tid; i < 4096; i += 256) {
        int row = i >> 7, seg = i & 127;
        *(uint4*)(swhi + row * WSTRIDE + seg * 8) =
            *(const uint4*)(vhi + (size_t)(m0 + row) * HH + seg * 8);
        *(uint4*)(swlo + row * WSTRIDE + seg * 8) =
            *(const uint4*)(vlo + (size_t)(m0 + row) * HH + seg * 8);
    }

    // ---- init h state + splits ----
    for (int e = gid; e < BB * HH; e += RB * 256) {
        float v = h0[e];
        hf[e] = v;
        __nv_bfloat16 hi = __float2bfloat16(v);
        hbh[e] = hi;
        hbl[e] = __float2bfloat16(v - __bfloat162float(hi));
    }
    grid_bar();

    const uint32_t a_base = (uint32_t)((lane & 15) * WSTRIDE + (lane >> 4) * 8) * 2;
    const uint32_t b_base = (uint32_t)((w * 8 + (lane & 7)) * HSTRIDE + (lane >> 3) * 8) * 2;

    for (int t = 0; t < TT; t++) {
        float acc0[4] = {0.f, 0.f, 0.f, 0.f};
        float acc1[4] = {0.f, 0.f, 0.f, 0.f};

        // stage chunk 0
#pragma unroll
        for (int i = 0; i < 8; i++) {
            int idx = tid + i * 256;
            int s = idx >> 10, rem = idx & 1023, row = rem >> 4, seg = rem & 15;
            uint32_t dst = hbase + s * 17408 + row * 272 + seg * 16;
            const __nv_bfloat16* src = (s ? hbl : hbh) + (size_t)row * HH + seg * 8;
            CP_ASYNC16(dst, src);
        }
        CP_COMMIT;

        for (int c = 0; c < 8; c++) {
            if (c < 7) {
                const int kt = (c + 1) * 128;
                const uint32_t bufo = (uint32_t)((c + 1) & 1) * 34816;
#pragma unroll
                for (int i = 0; i < 8; i++) {
                    int idx = tid + i * 256;
                    int s = idx >> 10, rem = idx & 1023, row = rem >> 4, seg = rem & 15;
                    uint32_t dst = hbase + bufo + s * 17408 + row * 272 + seg * 16;
                    const __nv_bfloat16* src = (s ? hbl : hbh) + (size_t)row * HH + kt + seg * 8;
                    CP_ASYNC16(dst, src);
                }
                CP_COMMIT;
                CP_WAIT1;
            } else {
                CP_WAIT0;
            }
            __syncthreads();

            const uint32_t hb = hbase + (uint32_t)(c & 1) * 34816;
            const uint32_t hl = hb + 17408;
#pragma unroll
            for (int ksh = 0; ksh < 4; ksh++) {
                uint32_t bh4[4], bl4[4];
                ldmx4(bh4, hb + b_base + ksh * 64);
                ldmx4(bl4, hl + b_base + ksh * 64);
#pragma unroll
                for (int sub = 0; sub < 2; sub++) {
                    const uint32_t kb = (uint32_t)(c * 128 + ksh * 32 + sub * 16) * 2;
                    uint32_t ah0[4], al0[4], ah1[4], al1[4];
                    ldmx4(ah0, smb + a_base + kb);
                    ldmx4(al0, smb + 66048 + a_base + kb);
                    ldmx4(ah1, smb + a_base + 16 * WSTRIDE * 2 + kb);
                    ldmx4(al1, smb + 66048 + a_base + 16 * WSTRIDE * 2 + kb);
                    uint32_t* bh = &bh4[sub * 2];
                    uint32_t* bl = &bl4[sub * 2];
                    mma16816(acc0, ah0, bh);
                    mma16816(acc0, ah0, bl);
                    mma16816(acc0, al0, bh);
                    mma16816(acc1, ah1, bh);
                    mma16816(acc1, ah1, bl);
                    mma16816(acc1, al1, bh);
                }
            }
            __syncthreads();
        }

        // ---- write gate pre-activations: gates[b][3H] ----
        {
            int row = m0 + (lane >> 2);
            int b   = w * 8 + (lane & 3) * 2;
            gates[(size_t)b * G3 + row]             = acc0[0];
            gates[(size_t)(b + 1) * G3 + row]       = acc0[1];
            gates[(size_t)b * G3 + row + 8]         = acc0[2];
            gates[(size_t)(b + 1) * G3 + row + 8]   = acc0[3];
            gates[(size_t)b * G3 + row + 16]        = acc1[0];
            gates[(size_t)(b + 1) * G3 + row + 16]  = acc1[1];
            gates[(size_t)b * G3 + row + 24]        = acc1[2];
            gates[(size_t)(b + 1) * G3 + row + 24]  = acc1[3];
        }
        grid_bar();

        // ---- phase B: pointwise GRU update ----
        for (int e = gid; e < BB * HH; e += RB * 256) {
            int b = e >> 10, j = e & 1023;
            const float* xrow = xg + ((size_t)t * BB + b) * G3;
            float gr = __ldcg(&gates[(size_t)b * G3 + j]);
            float gz = __ldcg(&gates[(size_t)b * G3 + HH + j]);
            float gn = __ldcg(&gates[(size_t)b * G3 + 2 * HH + j]);
            float r = 1.f / (1.f + expf(-(xrow[j] + gr + bhh[j])));
            float z = 1.f / (1.f + expf(-(xrow[HH + j] + gz + bhh[HH + j])));
            float n = tanhf(xrow[2 * HH + j] + r * (gn + bhh[2 * HH + j]));
            float hp = hf[e];
            float hv = (1.f - z) * n + z * hp;
            hf[e] = hv;
            __nv_bfloat16 hi = __float2bfloat16(hv);
            hbh[e] = hi;
            hbl[e] = __float2bfloat16(hv - __bfloat162float(hi));
            Y[(size_t)t * BB * HH + e] = hv;
            if (hn != nullptr && t == TT - 1) hn[e] = hv;
        }
        grid_bar();
    }
}

// ---------------- launch -------------------------------------------------------
extern "C" void kernel_launch(void* const* d_in, const int* in_sizes, int n_in,
                              void* d_out, int out_size)
{
    const float* x   = (const float*)d_in[0];
    const float* h0  = (const float*)d_in[1];
    const float* Wih = (const float*)d_in[2];
    const float* Whh = (const float*)d_in[3];
    const float* bih = (const float*)d_in[4];
    const float* bhh = (const float*)d_in[5];
    float* out = (float*)d_out;

    float *xg, *y1, *hf, *gates;
    __nv_bfloat16 *xhi, *xlo, *whi, *wlo, *vhi, *vlo, *hbh, *hbl;
    cudaGetSymbolAddress((void**)&xg,    g_xg);
    cudaGetSymbolAddress((void**)&y1,    g_y1);
    cudaGetSymbolAddress((void**)&xhi,   g_xhi);
    cudaGetSymbolAddress((void**)&xlo,   g_xlo);
    cudaGetSymbolAddress((void**)&whi,   g_whi);
    cudaGetSymbolAddress((void**)&wlo,   g_wlo);
    cudaGetSymbolAddress((void**)&vhi,   g_vhi);
    cudaGetSymbolAddress((void**)&vlo,   g_vlo);
    cudaGetSymbolAddress((void**)&hf,    g_hf);
    cudaGetSymbolAddress((void**)&hbh,   g_hbh);
    cudaGetSymbolAddress((void**)&hbl,   g_hbl);
    cudaGetSymbolAddress((void**)&gates, g_gates);

    const int gemmSmem = 4 * 128 * SROW * 2;              // 73728 B
    const int recSmem  = 132096 + 2 * 34816;              // 201728 B
    static bool attr_set = false;
    if (!attr_set) {
        cudaFuncSetAttribute(gemm_xg_hmma,
                             cudaFuncAttributeMaxDynamicSharedMemorySize, gemmSmem);
        cudaFuncSetAttribute(gru_rec_hmma,
                             cudaFuncAttributeMaxDynamicSharedMemorySize, recSmem);
        attr_set = true;
    }

    const dim3 gemmGrid(G3 / 128, (TT * BB) / 128);       // 24 x 256
    const int  n4x = TT * BB * HH / 4;
    const int  n4w = G3 * HH / 4;
    const bool write_hn = (out_size >= TT * BB * HH + LL * BB * HH);

    for (int l = 0; l < LL; l++) {
        const float* Xin = (l == 0) ? x : y1;
        float* Y         = (l == 0) ? y1 : out;
        float* hn        = write_hn
            ? out + (size_t)TT * BB * HH + (size_t)l * BB * HH : nullptr;

        split_f32_kernel<<<(n4x + 255) / 256, 256>>>(Xin, xhi, xlo, n4x);
        split_f32_kernel<<<(n4w + 255) / 256, 256>>>(Wih + (size_t)l * G3 * HH,
                                                     whi, wlo, n4w);
        split_f32_kernel<<<(n4w + 255) / 256, 256>>>(Whh + (size_t)l * G3 * HH,
                                                     vhi, vlo, n4w);

        gemm_xg_hmma<<<gemmGrid, 256, gemmSmem>>>(xhi, xlo, whi, wlo,
                                                  bih + (size_t)l * G3, xg);

        gru_rec_hmma<<<RB, 256, recSmem>>>(h0 + (size_t)l * BB * HH,
                                           vhi, vlo, bhh + (size_t)l * G3,
                                           xg, Y, hn, hf, hbh, hbl, gates);
    }
}

// round 8
// speedup vs baseline: 3.4853x; 1.4265x over previous
#include <cuda_runtime.h>
#include <cuda_bf16.h>
#include <math.h>
#include <stdint.h>

#define TT 512
#define BB 64
#define HH 1024
#define G3 3072   // 3*H
#define LL 2
#define RB 128         // recurrence blocks, 1/SM, each owns 8 output columns j
#define WSTRIDE 1032   // W smem row stride (bf16 elem): 2064B -> 16B/row shift, conflict-free
#define HSTRIDE 136    // h tile row stride (bf16 elem): 272B  -> 16B/row shift, conflict-free

// ---------------- scratch (static device arrays; no cudaMalloc) -------------
__device__ float g_xg[(size_t)TT * BB * G3];          // input gates, current layer
__device__ float g_y1[(size_t)TT * BB * HH];          // layer-1 output sequence
__device__ __nv_bfloat16 g_xhi[(size_t)TT * BB * HH]; // split X (hi)
__device__ __nv_bfloat16 g_xlo[(size_t)TT * BB * HH]; // split X (lo)
__device__ __nv_bfloat16 g_whi[(size_t)G3 * HH];      // split Wih (hi)
__device__ __nv_bfloat16 g_wlo[(size_t)G3 * HH];      // split Wih (lo)
__device__ __nv_bfloat16 g_vhi[(size_t)G3 * HH];      // split Whh (hi)
__device__ __nv_bfloat16 g_vlo[(size_t)G3 * HH];      // split Whh (lo)
__device__ __nv_bfloat16 g_hbh[2][BB * HH];           // ping-pong h split hi [b][k]
__device__ __nv_bfloat16 g_hbl[2][BB * HH];           // ping-pong h split lo [b][k]

// grid-barrier state
__device__ unsigned g_bar_count = 0;
__device__ unsigned g_bar_gen   = 0;

// ---------------- tiny first launch: makes the recurrence launch #6 for ncu --
__global__ void bar_reset_kernel() { g_bar_count = 0; }

// ======================= warp MMA helpers (sm_80+ PTX, valid on compute_103) ==
__device__ __forceinline__ uint32_t smem_u32(const void* p) {
    uint32_t a;
    asm("{ .reg .u64 t; cvta.to.shared.u64 t, %1; cvt.u32.u64 %0, t; }"
        : "=r"(a) : "l"(p));
    return a;
}
__device__ __forceinline__ void ldmx4(uint32_t* r, uint32_t addr) {
    asm volatile("ldmatrix.sync.aligned.m8n8.x4.shared.b16 {%0,%1,%2,%3}, [%4];"
        : "=r"(r[0]), "=r"(r[1]), "=r"(r[2]), "=r"(r[3]) : "r"(addr));
}
__device__ __forceinline__ void mma16816(float* c, const uint32_t* a, const uint32_t* b) {
    asm volatile("mma.sync.aligned.m16n8k16.row.col.f32.bf16.bf16.f32 "
        "{%0,%1,%2,%3}, {%4,%5,%6,%7}, {%8,%9}, {%0,%1,%2,%3};"
        : "+f"(c[0]), "+f"(c[1]), "+f"(c[2]), "+f"(c[3])
        : "r"(a[0]), "r"(a[1]), "r"(a[2]), "r"(a[3]), "r"(b[0]), "r"(b[1]));
}
#define CP_ASYNC16(dst, src) \
    asm volatile("cp.async.cg.shared.global [%0], [%1], 16;" :: "r"(dst), "l"(src))
#define CP_COMMIT   asm volatile("cp.async.commit_group;" ::: "memory")
#define CP_WAIT1    asm volatile("cp.async.wait_group 1;" ::: "memory")
#define CP_WAIT0    asm volatile("cp.async.wait_group 0;" ::: "memory")

// ---------------- fp32 -> (hi, lo) bf16 split --------------------------------
__global__ void split_f32_kernel(const float* __restrict__ src,
                                 __nv_bfloat16* __restrict__ hi,
                                 __nv_bfloat16* __restrict__ lo, int n4)
{
    int i = blockIdx.x * blockDim.x + threadIdx.x;
    if (i >= n4) return;
    float4 v = ((const float4*)src)[i];
    float f[4] = {v.x, v.y, v.z, v.w};
    uint32_t ph[2], pl[2];
#pragma unroll
    for (int q = 0; q < 2; q++) {
        __nv_bfloat16 h0 = __float2bfloat16(f[q * 2 + 0]);
        __nv_bfloat16 h1 = __float2bfloat16(f[q * 2 + 1]);
        __nv_bfloat16 l0 = __float2bfloat16(f[q * 2 + 0] - __bfloat162float(h0));
        __nv_bfloat16 l1 = __float2bfloat16(f[q * 2 + 1] - __bfloat162float(h1));
        ph[q] = (uint32_t)__bfloat16_as_ushort(h0) | ((uint32_t)__bfloat16_as_ushort(h1) << 16);
        pl[q] = (uint32_t)__bfloat16_as_ushort(l0) | ((uint32_t)__bfloat16_as_ushort(l1) << 16);
    }
    ((uint2*)hi)[i] = make_uint2(ph[0], ph[1]);
    ((uint2*)lo)[i] = make_uint2(pl[0], pl[1]);
}

// ---------------- HMMA bf16-split input GEMM (validated, unchanged) -----------
#define SROW 72
__global__ void __launch_bounds__(256, 1)
gemm_xg_hmma(const __nv_bfloat16* __restrict__ Xhi, const __nv_bfloat16* __restrict__ Xlo,
             const __nv_bfloat16* __restrict__ Whi, const __nv_bfloat16* __restrict__ Wlo,
             const float* __restrict__ bias, float* __restrict__ C)
{
    extern __shared__ __nv_bfloat16 sm[];
    const int TILE = 128 * SROW;

    const int tid  = threadIdx.x;
    const int lane = tid & 31;
    const int wid  = tid >> 5;
    const int wm   = wid & 1;
    const int wn   = wid >> 1;
    const int n0   = blockIdx.x * 128;
    const int m0   = blockIdx.y * 128;

    const uint32_t smb = smem_u32(sm);

    float acc[4][4][4];
#pragma unroll
    for (int i = 0; i < 4; i++)
#pragma unroll
        for (int j = 0; j < 4; j++)
#pragma unroll
            for (int q = 0; q < 4; q++) acc[i][j][q] = 0.f;

    const int arow = (wm * 64 + (lane & 15)) * SROW + (lane >> 4) * 8;
    const int brow = (wn * 32 + (lane & 7) + ((lane >> 4) << 3)) * SROW
                   + ((lane >> 3) & 1) * 8;

    const __nv_bfloat16* srcs[4] = {
        Xhi + (size_t)m0 * HH, Xlo + (size_t)m0 * HH,
        Whi + (size_t)n0 * HH, Wlo + (size_t)n0 * HH };

    for (int ch = 0; ch < 16; ch++) {
        const int kt = ch * 64;
#pragma unroll
        for (int tile = 0; tile < 4; tile++) {
            const __nv_bfloat16* src = srcs[tile] + kt;
#pragma unroll
            for (int it = 0; it < 4; it++) {
                int idx = tid + it * 256;
                int row = idx >> 3, c8 = idx & 7;
                float4 v = *(const float4*)(src + (size_t)row * HH + c8 * 8);
                *(float4*)(sm + tile * TILE + row * SROW + c8 * 8) = v;
            }
        }
        __syncthreads();

#pragma unroll
        for (int ks = 0; ks < 4; ks++) {
            uint32_t ahi[4][4], alo[4][4], bhi[4][2], blo[4][2];
#pragma unroll
            for (int mf = 0; mf < 4; mf++) {
                uint32_t aoff = (uint32_t)(arow + mf * 16 * SROW + ks * 16) * 2;
                ldmx4(ahi[mf], smb + 0 * TILE * 2 + aoff);
                ldmx4(alo[mf], smb + 1 * TILE * 2 + aoff);
            }
#pragma unroll
            for (int pr = 0; pr < 2; pr++) {
                uint32_t boff = (uint32_t)(brow + pr * 16 * SROW + ks * 16) * 2;
                uint32_t rh[4], rl[4];
                ldmx4(rh, smb + 2 * TILE * 2 + boff);
                ldmx4(rl, smb + 3 * TILE * 2 + boff);
                bhi[pr * 2 + 0][0] = rh[0]; bhi[pr * 2 + 0][1] = rh[1];
                bhi[pr * 2 + 1][0] = rh[2]; bhi[pr * 2 + 1][1] = rh[3];
                blo[pr * 2 + 0][0] = rl[0]; blo[pr * 2 + 0][1] = rl[1];
                blo[pr * 2 + 1][0] = rl[2]; blo[pr * 2 + 1][1] = rl[3];
            }
#pragma unroll
            for (int mf = 0; mf < 4; mf++)
#pragma unroll
                for (int nf = 0; nf < 4; nf++) {
                    mma16816(acc[mf][nf], ahi[mf], bhi[nf]);
                    mma16816(acc[mf][nf], ahi[mf], blo[nf]);
                    mma16816(acc[mf][nf], alo[mf], bhi[nf]);
                }
        }
        __syncthreads();
    }

#pragma unroll
    for (int mf = 0; mf < 4; mf++) {
        int row = m0 + wm * 64 + mf * 16 + (lane >> 2);
#pragma unroll
        for (int nf = 0; nf < 4; nf++) {
            int col = n0 + wn * 32 + nf * 8 + (lane & 3) * 2;
            float b0 = bias[col], b1 = bias[col + 1];
            float2 v0 = make_float2(acc[mf][nf][0] + b0, acc[mf][nf][1] + b1);
            float2 v1 = make_float2(acc[mf][nf][2] + b0, acc[mf][nf][3] + b1);
            *(float2*)&C[(size_t)row * G3 + col]       = v0;
            *(float2*)&C[(size_t)(row + 8) * G3 + col] = v1;
        }
    }
}

// ---------------- software grid barrier (RB blocks) ---------------------------
__device__ __forceinline__ void grid_bar()
{
    __threadfence();
    __syncthreads();
    if (threadIdx.x == 0) {
        unsigned gen = *(volatile unsigned*)&g_bar_gen;
        if (atomicAdd(&g_bar_count, 1u) == RB - 1) {
            g_bar_count = 0;
            __threadfence();
            *(volatile unsigned*)&g_bar_gen = gen + 1;
        } else {
            while (*(volatile unsigned*)&g_bar_gen == gen) __nanosleep(32);
        }
        __threadfence();
    }
    __syncthreads();
}

// ---------------- persistent HMMA GRU recurrence, j-aligned -------------------
// Block bx owns output columns j0 = bx*8 .. +8 for ALL gates.
// W smem: 32 phys rows = [r(j0..j0+7) | z | n | pad] x K=1024, hi+lo (132 KB).
// Per step: stage full h (hi+lo) in 8 x 128k cp.async chunks; MMA; gates -> smem;
// local pointwise update (h master in regs); write next h splits; ONE grid_bar.
__global__ void __launch_bounds__(256, 1)
gru_rec_v2(const float* __restrict__ h0,
           const __nv_bfloat16* __restrict__ vhi,
           const __nv_bfloat16* __restrict__ vlo,
           const float* __restrict__ bhh,
           const float* __restrict__ xg,     // [T,B,3H]
           float* __restrict__ Y,            // [T,B,H]
           float* __restrict__ hn,           // [B,H] or null
           __nv_bfloat16* __restrict__ hbh0, __nv_bfloat16* __restrict__ hbl0,
           __nv_bfloat16* __restrict__ hbh1, __nv_bfloat16* __restrict__ hbl1)
{
    extern __shared__ char smc[];
    __nv_bfloat16* swhi = (__nv_bfloat16*)smc;                    // 66048 B
    __nv_bfloat16* swlo = (__nv_bfloat16*)(smc + 66048);          // 66048 B
    float* accbuf       = (float*)(smc + 201728);                 // 32 x 66 fp32
    const uint32_t smb   = smem_u32(smc);
    const uint32_t hbase = smb + 132096;                          // 2 x 34816 B dbuf

    const int tid  = threadIdx.x;
    const int lane = tid & 31;
    const int w    = tid >> 5;
    const int j0   = blockIdx.x * 8;

    // ---- preload W slice: phys row p -> gate p>>3, col j0+(p&7); p>=24 pad ----
    for (int i = tid; i < 32 * 128; i += 256) {
        int p = i >> 7, seg = i & 127;
        uint4 vh = make_uint4(0, 0, 0, 0), vl = make_uint4(0, 0, 0, 0);
        if (p < 24) {
            size_t off = ((size_t)(p >> 3) * HH + j0 + (p & 7)) * HH + seg * 8;
            vh = *(const uint4*)(vhi + off);
            vl = *(const uint4*)(vlo + off);
        }
        *(uint4*)(swhi + p * WSTRIDE + seg * 8) = vh;
        *(uint4*)(swlo + p * WSTRIDE + seg * 8) = vl;
    }

    // ---- h master state in registers: thread owns (b, j0+jj), (b, j0+jj+1) ----
    const int pb = tid >> 2;           // batch 0..63
    const int pj = (tid & 3) * 2;      // jj 0,2,4,6
    float hm0, hm1;
    {
        hm0 = h0[(size_t)pb * HH + j0 + pj];
        hm1 = h0[(size_t)pb * HH + j0 + pj + 1];
        __nv_bfloat16 a = __float2bfloat16(hm0), b = __float2bfloat16(hm1);
        __nv_bfloat16 c = __float2bfloat16(hm0 - __bfloat162float(a));
        __nv_bfloat16 d = __float2bfloat16(hm1 - __bfloat162float(b));
        uint32_t ph = (uint32_t)__bfloat16_as_ushort(a) | ((uint32_t)__bfloat16_as_ushort(b) << 16);
        uint32_t pl = (uint32_t)__bfloat16_as_ushort(c) | ((uint32_t)__bfloat16_as_ushort(d) << 16);
        *(uint32_t*)&hbh0[(size_t)pb * HH + j0 + pj] = ph;
        *(uint32_t*)&hbl0[(size_t)pb * HH + j0 + pj] = pl;
    }
    // hoisted biases for phase B
    const float br0 = bhh[j0 + pj],          br1 = bhh[j0 + pj + 1];
    const float bz0 = bhh[HH + j0 + pj],     bz1 = bhh[HH + j0 + pj + 1];
    const float bn0 = bhh[2 * HH + j0 + pj], bn1 = bhh[2 * HH + j0 + pj + 1];

    grid_bar();

    // ldmatrix bases
    // A (W): warp's m-tile = (w>>2); lanes 0-15 rows, 16-31 rows k+8
    const uint32_t a_base = (uint32_t)(((w >> 2) * 16 + (lane & 15)) * WSTRIDE
                                       + (lane >> 4) * 8) * 2;
    // B (h): warp's 16 batches = 16*(w&3); x4 = 2 n-frags (8+8 batches) x k16
    const uint32_t b_base = (uint32_t)((16 * (w & 3) + (lane & 7) + ((lane >> 4) << 3)) * HSTRIDE
                                       + ((lane >> 3) & 1) * 8) * 2;

    for (int t = 0; t < TT; t++) {
        const __nv_bfloat16* srch = (t & 1) ? hbh1 : hbh0;
        const __nv_bfloat16* srcl = (t & 1) ? hbl1 : hbl0;

        float acc0[4] = {0.f, 0.f, 0.f, 0.f};
        float acc1[4] = {0.f, 0.f, 0.f, 0.f};

        // stage chunk 0
#pragma unroll
        for (int i = 0; i < 8; i++) {
            int idx = tid + i * 256;
            int s = idx >> 10, rem = idx & 1023, row = rem >> 4, seg = rem & 15;
            uint32_t dst = hbase + s * 17408 + row * 272 + seg * 16;
            const __nv_bfloat16* src = (s ? srcl : srch) + (size_t)row * HH + seg * 8;
            CP_ASYNC16(dst, src);
        }
        CP_COMMIT;

        for (int c = 0; c < 8; c++) {
            if (c < 7) {
                const int kt = (c + 1) * 128;
                const uint32_t bufo = (uint32_t)((c + 1) & 1) * 34816;
#pragma unroll
                for (int i = 0; i < 8; i++) {
                    int idx = tid + i * 256;
                    int s = idx >> 10, rem = idx & 1023, row = rem >> 4, seg = rem & 15;
                    uint32_t dst = hbase + bufo + s * 17408 + row * 272 + seg * 16;
                    const __nv_bfloat16* src = (s ? srcl : srch) + (size_t)row * HH + kt + seg * 8;
                    CP_ASYNC16(dst, src);
                }
                CP_COMMIT;
                CP_WAIT1;
            } else {
                CP_WAIT0;
            }
            __syncthreads();

            const uint32_t hb = hbase + (uint32_t)(c & 1) * 34816;
#pragma unroll
            for (int kk = 0; kk < 8; kk++) {
                uint32_t bh[4], bl[4], ah[4], al[4];
                ldmx4(bh, hb + b_base + kk * 32);
                ldmx4(bl, hb + 17408 + b_base + kk * 32);
                const uint32_t koffb = (uint32_t)(c * 128 + kk * 16) * 2;
                ldmx4(ah, smb + a_base + koffb);
                ldmx4(al, smb + 66048 + a_base + koffb);
                mma16816(acc0, ah, &bh[0]);
                mma16816(acc0, ah, &bl[0]);
                mma16816(acc0, al, &bh[0]);
                mma16816(acc1, ah, &bh[2]);
                mma16816(acc1, ah, &bl[2]);
                mma16816(acc1, al, &bh[2]);
            }
            __syncthreads();
        }

        // ---- gates -> smem (local!) ----
        {
            int row = (w >> 2) * 16 + (lane >> 2);
            int col = 16 * (w & 3) + (lane & 3) * 2;
            accbuf[row * 66 + col]           = acc0[0];
            accbuf[row * 66 + col + 1]       = acc0[1];
            accbuf[(row + 8) * 66 + col]     = acc0[2];
            accbuf[(row + 8) * 66 + col + 1] = acc0[3];
            accbuf[row * 66 + col + 8]           = acc1[0];
            accbuf[row * 66 + col + 9]           = acc1[1];
            accbuf[(row + 8) * 66 + col + 8]     = acc1[2];
            accbuf[(row + 8) * 66 + col + 9]     = acc1[3];
        }
        __syncthreads();

        // ---- pointwise GRU update, fully local ----
        {
            const float* xrow = xg + ((size_t)t * BB + pb) * G3;
            float2 xr = *(const float2*)&xrow[j0 + pj];
            float2 xz = *(const float2*)&xrow[HH + j0 + pj];
            float2 xn = *(const float2*)&xrow[2 * HH + j0 + pj];
            float gr0 = accbuf[pj * 66 + pb],        gr1 = accbuf[(pj + 1) * 66 + pb];
            float gz0 = accbuf[(8 + pj) * 66 + pb],  gz1 = accbuf[(9 + pj) * 66 + pb];
            float gn0 = accbuf[(16 + pj) * 66 + pb], gn1 = accbuf[(17 + pj) * 66 + pb];

            float r0 = 1.f / (1.f + expf(-(xr.x + gr0 + br0)));
            float r1 = 1.f / (1.f + expf(-(xr.y + gr1 + br1)));
            float z0 = 1.f / (1.f + expf(-(xz.x + gz0 + bz0)));
            float z1 = 1.f / (1.f + expf(-(xz.y + gz1 + bz1)));
            float n0 = tanhf(xn.x + r0 * (gn0 + bn0));
            float n1 = tanhf(xn.y + r1 * (gn1 + bn1));
            hm0 = (1.f - z0) * n0 + z0 * hm0;
            hm1 = (1.f - z1) * n1 + z1 * hm1;

            __nv_bfloat16 a = __float2bfloat16(hm0), b = __float2bfloat16(hm1);
            __nv_bfloat16 cc = __float2bfloat16(hm0 - __bfloat162float(a));
            __nv_bfloat16 dd = __float2bfloat16(hm1 - __bfloat162float(b));
            uint32_t ph = (uint32_t)__bfloat16_as_ushort(a) | ((uint32_t)__bfloat16_as_ushort(b) << 16);
            uint32_t pl = (uint32_t)__bfloat16_as_ushort(cc) | ((uint32_t)__bfloat16_as_ushort(dd) << 16);
            __nv_bfloat16* dsth = (t & 1) ? hbh0 : hbh1;   // buffer (t+1)&1
            __nv_bfloat16* dstl = (t & 1) ? hbl0 : hbl1;
            *(uint32_t*)&dsth[(size_t)pb * HH + j0 + pj] = ph;
            *(uint32_t*)&dstl[(size_t)pb * HH + j0 + pj] = pl;
            *(float2*)&Y[((size_t)t * BB + pb) * HH + j0 + pj] = make_float2(hm0, hm1);
            if (hn != nullptr && t == TT - 1)
                *(float2*)&hn[(size_t)pb * HH + j0 + pj] = make_float2(hm0, hm1);
        }

        grid_bar();   // single barrier per step (ping-pong h makes this safe)
    }
}

// ---------------- launch -------------------------------------------------------
extern "C" void kernel_launch(void* const* d_in, const int* in_sizes, int n_in,
                              void* d_out, int out_size)
{
    const float* x   = (const float*)d_in[0];
    const float* h0  = (const float*)d_in[1];
    const float* Wih = (const float*)d_in[2];
    const float* Whh = (const float*)d_in[3];
    const float* bih = (const float*)d_in[4];
    const float* bhh = (const float*)d_in[5];
    float* out = (float*)d_out;

    float *xg, *y1;
    __nv_bfloat16 *xhi, *xlo, *whi, *wlo, *vhi, *vlo, *hbh, *hbl;
    cudaGetSymbolAddress((void**)&xg,  g_xg);
    cudaGetSymbolAddress((void**)&y1,  g_y1);
    cudaGetSymbolAddress((void**)&xhi, g_xhi);
    cudaGetSymbolAddress((void**)&xlo, g_xlo);
    cudaGetSymbolAddress((void**)&whi, g_whi);
    cudaGetSymbolAddress((void**)&wlo, g_wlo);
    cudaGetSymbolAddress((void**)&vhi, g_vhi);
    cudaGetSymbolAddress((void**)&vlo, g_vlo);
    cudaGetSymbolAddress((void**)&hbh, g_hbh);
    cudaGetSymbolAddress((void**)&hbl, g_hbl);

    const int gemmSmem = 4 * 128 * SROW * 2;               // 73728 B
    const int recSmem  = 132096 + 2 * 34816 + 32 * 66 * 4; // 210176 B
    static bool attr_set = false;
    if (!attr_set) {
        cudaFuncSetAttribute(gemm_xg_hmma,
                             cudaFuncAttributeMaxDynamicSharedMemorySize, gemmSmem);
        cudaFuncSetAttribute(gru_rec_v2,
                             cudaFuncAttributeMaxDynamicSharedMemorySize, recSmem);
        attr_set = true;
    }

    const dim3 gemmGrid(G3 / 128, (TT * BB) / 128);        // 24 x 256
    const int  n4x = TT * BB * HH / 4;
    const int  n4w = G3 * HH / 4;
    const bool write_hn = (out_size >= TT * BB * HH + LL * BB * HH);

    bar_reset_kernel<<<1, 1>>>();   // also shifts ncu -s 5 onto the recurrence

    for (int l = 0; l < LL; l++) {
        const float* Xin = (l == 0) ? x : y1;
        float* Y         = (l == 0) ? y1 : out;
        float* hn        = write_hn
            ? out + (size_t)TT * BB * HH + (size_t)l * BB * HH : nullptr;

        split_f32_kernel<<<(n4x + 255) / 256, 256>>>(Xin, xhi, xlo, n4x);
        split_f32_kernel<<<(n4w + 255) / 256, 256>>>(Wih + (size_t)l * G3 * HH,
                                                     whi, wlo, n4w);
        split_f32_kernel<<<(n4w + 255) / 256, 256>>>(Whh + (size_t)l * G3 * HH,
                                                     vhi, vlo, n4w);

        gemm_xg_hmma<<<gemmGrid, 256, gemmSmem>>>(xhi, xlo, whi, wlo,
                                                  bih + (size_t)l * G3, xg);

        gru_rec_v2<<<RB, 256, recSmem>>>(h0 + (size_t)l * BB * HH,
                                         vhi, vlo, bhh + (size_t)l * G3,
                                         xg, Y, hn,
                                         hbh, hbl,
                                         hbh + BB * HH, hbl + BB * HH);
    }
}

// round 9
// speedup vs baseline: 3.5212x; 1.0103x over previous
#include <cuda_runtime.h>
#include <cuda_bf16.h>
#include <math.h>
#include <stdint.h>

#define TT 512
#define BB 64
#define HH 1024
#define G3 3072   // 3*H
#define LL 2
#define RB 128         // recurrence blocks, 1/SM, each owns 8 output columns j
#define WSTRIDE 1032   // W smem row stride (bf16 elem): 2064B -> 16B/row shift, conflict-free
#define HSTRIDE 136    // h tile row stride (bf16 elem): 272B  -> 16B/row shift, conflict-free

// smem layout (bytes) for gru_rec_v3
#define OFF_WHI   0u        // 24 rows x 2064B = 49536
#define OFF_WLO   49536u    // 32 rows x 2064B = 66048 (rows 24-31 zeroed)
#define OFF_HBUF  115584u   // 3 bufs x 34816 (hi 17408 + lo 17408)
#define OFF_ACC   220032u   // 32 x 66 fp32 = 8448
#define REC_SMEM  228480u

// ---------------- scratch (static device arrays; no cudaMalloc) -------------
__device__ float g_xg[(size_t)TT * BB * G3];          // input gates, current layer
__device__ float g_y1[(size_t)TT * BB * HH];          // layer-1 output sequence
__device__ __nv_bfloat16 g_xhi[(size_t)TT * BB * HH]; // split X (hi)
__device__ __nv_bfloat16 g_xlo[(size_t)TT * BB * HH]; // split X (lo)
__device__ __nv_bfloat16 g_whi[(size_t)G3 * HH];      // split Wih (hi)
__device__ __nv_bfloat16 g_wlo[(size_t)G3 * HH];      // split Wih (lo)
__device__ __nv_bfloat16 g_vhi[(size_t)G3 * HH];      // split Whh (hi)
__device__ __nv_bfloat16 g_vlo[(size_t)G3 * HH];      // split Whh (lo)
__device__ __nv_bfloat16 g_hbh[2][BB * HH];           // ping-pong h split hi [b][k]
__device__ __nv_bfloat16 g_hbl[2][BB * HH];           // ping-pong h split lo [b][k]

// grid-barrier state
__device__ unsigned g_bar_count = 0;
__device__ unsigned g_bar_gen   = 0;

// ---------------- tiny first launch (also aligns ncu -s 5) -------------------
__global__ void bar_reset_kernel() { g_bar_count = 0; }

// ======================= warp MMA helpers =====================================
__device__ __forceinline__ uint32_t smem_u32(const void* p) {
    uint32_t a;
    asm("{ .reg .u64 t; cvta.to.shared.u64 t, %1; cvt.u32.u64 %0, t; }"
        : "=r"(a) : "l"(p));
    return a;
}
__device__ __forceinline__ void ldmx4(uint32_t* r, uint32_t addr) {
    asm volatile("ldmatrix.sync.aligned.m8n8.x4.shared.b16 {%0,%1,%2,%3}, [%4];"
        : "=r"(r[0]), "=r"(r[1]), "=r"(r[2]), "=r"(r[3]) : "r"(addr));
}
__device__ __forceinline__ void mma16816(float* c, const uint32_t* a, const uint32_t* b) {
    asm volatile("mma.sync.aligned.m16n8k16.row.col.f32.bf16.bf16.f32 "
        "{%0,%1,%2,%3}, {%4,%5,%6,%7}, {%8,%9}, {%0,%1,%2,%3};"
        : "+f"(c[0]), "+f"(c[1]), "+f"(c[2]), "+f"(c[3])
        : "r"(a[0]), "r"(a[1]), "r"(a[2]), "r"(a[3]), "r"(b[0]), "r"(b[1]));
}
#define CP_ASYNC16(dst, src) \
    asm volatile("cp.async.cg.shared.global [%0], [%1], 16;" :: "r"(dst), "l"(src))
#define CP_COMMIT   asm volatile("cp.async.commit_group;" ::: "memory")
#define CP_WAIT1    asm volatile("cp.async.wait_group 1;" ::: "memory")
#define CP_WAIT0    asm volatile("cp.async.wait_group 0;" ::: "memory")

// ---------------- fp32 -> (hi, lo) bf16 split --------------------------------
__global__ void split_f32_kernel(const float* __restrict__ src,
                                 __nv_bfloat16* __restrict__ hi,
                                 __nv_bfloat16* __restrict__ lo, int n4)
{
    int i = blockIdx.x * blockDim.x + threadIdx.x;
    if (i >= n4) return;
    float4 v = ((const float4*)src)[i];
    float f[4] = {v.x, v.y, v.z, v.w};
    uint32_t ph[2], pl[2];
#pragma unroll
    for (int q = 0; q < 2; q++) {
        __nv_bfloat16 h0 = __float2bfloat16(f[q * 2 + 0]);
        __nv_bfloat16 h1 = __float2bfloat16(f[q * 2 + 1]);
        __nv_bfloat16 l0 = __float2bfloat16(f[q * 2 + 0] - __bfloat162float(h0));
        __nv_bfloat16 l1 = __float2bfloat16(f[q * 2 + 1] - __bfloat162float(h1));
        ph[q] = (uint32_t)__bfloat16_as_ushort(h0) | ((uint32_t)__bfloat16_as_ushort(h1) << 16);
        pl[q] = (uint32_t)__bfloat16_as_ushort(l0) | ((uint32_t)__bfloat16_as_ushort(l1) << 16);
    }
    ((uint2*)hi)[i] = make_uint2(ph[0], ph[1]);
    ((uint2*)lo)[i] = make_uint2(pl[0], pl[1]);
}

// ---------------- HMMA bf16-split input GEMM (validated, unchanged) -----------
#define SROW 72
__global__ void __launch_bounds__(256, 1)
gemm_xg_hmma(const __nv_bfloat16* __restrict__ Xhi, const __nv_bfloat16* __restrict__ Xlo,
             const __nv_bfloat16* __restrict__ Whi, const __nv_bfloat16* __restrict__ Wlo,
             const float* __restrict__ bias, float* __restrict__ C)
{
    extern __shared__ __nv_bfloat16 sm[];
    const int TILE = 128 * SROW;

    const int tid  = threadIdx.x;
    const int lane = tid & 31;
    const int wid  = tid >> 5;
    const int wm   = wid & 1;
    const int wn   = wid >> 1;
    const int n0   = blockIdx.x * 128;
    const int m0   = blockIdx.y * 128;

    const uint32_t smb = smem_u32(sm);

    float acc[4][4][4];
#pragma unroll
    for (int i = 0; i < 4; i++)
#pragma unroll
        for (int j = 0; j < 4; j++)
#pragma unroll
            for (int q = 0; q < 4; q++) acc[i][j][q] = 0.f;

    const int arow = (wm * 64 + (lane & 15)) * SROW + (lane >> 4) * 8;
    const int brow = (wn * 32 + (lane & 7) + ((lane >> 4) << 3)) * SROW
                   + ((lane >> 3) & 1) * 8;

    const __nv_bfloat16* srcs[4] = {
        Xhi + (size_t)m0 * HH, Xlo + (size_t)m0 * HH,
        Whi + (size_t)n0 * HH, Wlo + (size_t)n0 * HH };

    for (int ch = 0; ch < 16; ch++) {
        const int kt = ch * 64;
#pragma unroll
        for (int tile = 0; tile < 4; tile++) {
            const __nv_bfloat16* src = srcs[tile] + kt;
#pragma unroll
            for (int it = 0; it < 4; it++) {
                int idx = tid + it * 256;
                int row = idx >> 3, c8 = idx & 7;
                float4 v = *(const float4*)(src + (size_t)row * HH + c8 * 8);
                *(float4*)(sm + tile * TILE + row * SROW + c8 * 8) = v;
            }
        }
        __syncthreads();

#pragma unroll
        for (int ks = 0; ks < 4; ks++) {
            uint32_t ahi[4][4], alo[4][4], bhi[4][2], blo[4][2];
#pragma unroll
            for (int mf = 0; mf < 4; mf++) {
                uint32_t aoff = (uint32_t)(arow + mf * 16 * SROW + ks * 16) * 2;
                ldmx4(ahi[mf], smb + 0 * TILE * 2 + aoff);
                ldmx4(alo[mf], smb + 1 * TILE * 2 + aoff);
            }
#pragma unroll
            for (int pr = 0; pr < 2; pr++) {
                uint32_t boff = (uint32_t)(brow + pr * 16 * SROW + ks * 16) * 2;
                uint32_t rh[4], rl[4];
                ldmx4(rh, smb + 2 * TILE * 2 + boff);
                ldmx4(rl, smb + 3 * TILE * 2 + boff);
                bhi[pr * 2 + 0][0] = rh[0]; bhi[pr * 2 + 0][1] = rh[1];
                bhi[pr * 2 + 1][0] = rh[2]; bhi[pr * 2 + 1][1] = rh[3];
                blo[pr * 2 + 0][0] = rl[0]; blo[pr * 2 + 0][1] = rl[1];
                blo[pr * 2 + 1][0] = rl[2]; blo[pr * 2 + 1][1] = rl[3];
            }
#pragma unroll
            for (int mf = 0; mf < 4; mf++)
#pragma unroll
                for (int nf = 0; nf < 4; nf++) {
                    mma16816(acc[mf][nf], ahi[mf], bhi[nf]);
                    mma16816(acc[mf][nf], ahi[mf], blo[nf]);
                    mma16816(acc[mf][nf], alo[mf], bhi[nf]);
                }
        }
        __syncthreads();
    }

#pragma unroll
    for (int mf = 0; mf < 4; mf++) {
        int row = m0 + wm * 64 + mf * 16 + (lane >> 2);
#pragma unroll
        for (int nf = 0; nf < 4; nf++) {
            int col = n0 + wn * 32 + nf * 8 + (lane & 3) * 2;
            float b0 = bias[col], b1 = bias[col + 1];
            float2 v0 = make_float2(acc[mf][nf][0] + b0, acc[mf][nf][1] + b1);
            float2 v1 = make_float2(acc[mf][nf][2] + b0, acc[mf][nf][3] + b1);
            *(float2*)&C[(size_t)row * G3 + col]       = v0;
            *(float2*)&C[(size_t)(row + 8) * G3 + col] = v1;
        }
    }
}

// ---------------- software grid barrier (RB blocks) ---------------------------
__device__ __forceinline__ void grid_bar()
{
    __threadfence();
    __syncthreads();
    if (threadIdx.x == 0) {
        unsigned gen = *(volatile unsigned*)&g_bar_gen;
        if (atomicAdd(&g_bar_count, 1u) == RB - 1) {
            g_bar_count = 0;
            __threadfence();
            *(volatile unsigned*)&g_bar_gen = gen + 1;
        } else {
            while (*(volatile unsigned*)&g_bar_gen == gen) __nanosleep(32);
        }
        __threadfence();
    }
    __syncthreads();
}

// ---------------- persistent HMMA GRU recurrence, v3 --------------------------
// Round-9 changes vs v2: 3-deep cp.async pipeline, ONE __syncthreads per chunk,
// xg prefetched into registers at step start, hn write hoisted.
__global__ void __launch_bounds__(256, 1)
gru_rec_v3(const float* __restrict__ h0,
           const __nv_bfloat16* __restrict__ vhi,
           const __nv_bfloat16* __restrict__ vlo,
           const float* __restrict__ bhh,
           const float* __restrict__ xg,     // [T,B,3H]
           float* __restrict__ Y,            // [T,B,H]
           float* __restrict__ hn,           // [B,H] or null
           __nv_bfloat16* __restrict__ hbh0, __nv_bfloat16* __restrict__ hbl0,
           __nv_bfloat16* __restrict__ hbh1, __nv_bfloat16* __restrict__ hbl1)
{
    extern __shared__ char smc[];
    __nv_bfloat16* swhi = (__nv_bfloat16*)(smc + OFF_WHI);   // 24 rows
    __nv_bfloat16* swlo = (__nv_bfloat16*)(smc + OFF_WLO);   // 32 rows (24-31 zero)
    float* accbuf       = (float*)(smc + OFF_ACC);
    const uint32_t smb   = smem_u32(smc);
    const uint32_t hbase = smb + OFF_HBUF;

    const int tid  = threadIdx.x;
    const int lane = tid & 31;
    const int w    = tid >> 5;
    const int j0   = blockIdx.x * 8;

    // ---- preload W slice: row p -> gate p>>3, col j0+(p&7) ----
    for (int i = tid; i < 24 * 128; i += 256) {
        int p = i >> 7, seg = i & 127;
        size_t off = ((size_t)(p >> 3) * HH + j0 + (p & 7)) * HH + seg * 8;
        *(uint4*)(swhi + p * WSTRIDE + seg * 8) = *(const uint4*)(vhi + off);
        *(uint4*)(swlo + p * WSTRIDE + seg * 8) = *(const uint4*)(vlo + off);
    }
    // zero swlo pad rows 24-31 (read by A-tile1 lo ldmatrix; results discarded,
    // zeroing keeps NaNs out of smem-race territory)
    for (int i = tid; i < 8 * 128; i += 256) {
        int p = 24 + (i >> 7), seg = i & 127;
        *(uint4*)(swlo + p * WSTRIDE + seg * 8) = make_uint4(0, 0, 0, 0);
    }

    // ---- h master state in registers: thread owns (pb, j0+pj), (pb, j0+pj+1) --
    const int pb = tid >> 2;           // batch 0..63
    const int pj = (tid & 3) * 2;      // jj 0,2,4,6
    float hm0, hm1;
    {
        hm0 = h0[(size_t)pb * HH + j0 + pj];
        hm1 = h0[(size_t)pb * HH + j0 + pj + 1];
        __nv_bfloat16 a = __float2bfloat16(hm0), b = __float2bfloat16(hm1);
        __nv_bfloat16 c = __float2bfloat16(hm0 - __bfloat162float(a));
        __nv_bfloat16 d = __float2bfloat16(hm1 - __bfloat162float(b));
        uint32_t ph = (uint32_t)__bfloat16_as_ushort(a) | ((uint32_t)__bfloat16_as_ushort(b) << 16);
        uint32_t pl = (uint32_t)__bfloat16_as_ushort(c) | ((uint32_t)__bfloat16_as_ushort(d) << 16);
        *(uint32_t*)&hbh0[(size_t)pb * HH + j0 + pj] = ph;
        *(uint32_t*)&hbl0[(size_t)pb * HH + j0 + pj] = pl;
    }
    const float br0 = bhh[j0 + pj],          br1 = bhh[j0 + pj + 1];
    const float bz0 = bhh[HH + j0 + pj],     bz1 = bhh[HH + j0 + pj + 1];
    const float bn0 = bhh[2 * HH + j0 + pj], bn1 = bhh[2 * HH + j0 + pj + 1];

    grid_bar();

    // ldmatrix bases
    const uint32_t a_base = (uint32_t)(((w >> 2) * 16 + (lane & 15)) * WSTRIDE
                                       + (lane >> 4) * 8) * 2;
    const uint32_t b_base = (uint32_t)((16 * (w & 3) + (lane & 7) + ((lane >> 4) << 3)) * HSTRIDE
                                       + ((lane >> 3) & 1) * 8) * 2;

    // chunk staging: 8 cp.async x 256 threads = 32KB (hi 16KB + lo 16KB)
    auto stage = [&](const __nv_bfloat16* srch, const __nv_bfloat16* srcl,
                     int chunk, uint32_t bufo) {
        const int kt = chunk * 128;
#pragma unroll
        for (int i = 0; i < 8; i++) {
            int idx = tid + i * 256;
            int s = idx >> 10, rem = idx & 1023, row = rem >> 4, seg = rem & 15;
            uint32_t dst = hbase + bufo + s * 17408 + row * 272 + seg * 16;
            const __nv_bfloat16* src = (s ? srcl : srch) + (size_t)row * HH + kt + seg * 8;
            CP_ASYNC16(dst, src);
        }
        CP_COMMIT;
    };

    for (int t = 0; t < TT; t++) {
        const __nv_bfloat16* srch = (t & 1) ? hbh1 : hbh0;
        const __nv_bfloat16* srcl = (t & 1) ? hbl1 : hbl0;

        // prefetch xg for the pointwise phase (hidden behind the chunk loop)
        const float* xrow = xg + ((size_t)t * BB + pb) * G3;
        float2 xr = *(const float2*)&xrow[j0 + pj];
        float2 xz = *(const float2*)&xrow[HH + j0 + pj];
        float2 xn = *(const float2*)&xrow[2 * HH + j0 + pj];

        float acc0[4] = {0.f, 0.f, 0.f, 0.f};
        float acc1[4] = {0.f, 0.f, 0.f, 0.f};

        // prologue: chunks 0 and 1 in flight
        stage(srch, srcl, 0, 0);
        stage(srch, srcl, 1, 34816);

        for (int c = 0; c < 8; c++) {
            if (c < 7) { CP_WAIT1; } else { CP_WAIT0; }
            __syncthreads();                    // chunk c visible; buf (c+2)%3 free
            if (c + 2 < 8)
                stage(srch, srcl, c + 2, (uint32_t)((c + 2) % 3) * 34816);

            const uint32_t hb = hbase + (uint32_t)(c % 3) * 34816;
#pragma unroll
            for (int kk = 0; kk < 8; kk++) {
                uint32_t bh[4], bl[4], ah[4], al[4];
                ldmx4(bh, hb + b_base + kk * 32);
                ldmx4(bl, hb + 17408 + b_base + kk * 32);
                const uint32_t koffb = (uint32_t)(c * 128 + kk * 16) * 2;
                ldmx4(ah, smb + OFF_WHI + a_base + koffb);
                ldmx4(al, smb + OFF_WLO + a_base + koffb);
                mma16816(acc0, ah, &bh[0]);
                mma16816(acc0, ah, &bl[0]);
                mma16816(acc0, al, &bh[0]);
                mma16816(acc1, ah, &bh[2]);
                mma16816(acc1, ah, &bl[2]);
                mma16816(acc1, al, &bh[2]);
            }
        }

        // ---- gates -> smem (local) ----
        __syncthreads();   // all MMA reads of last chunk done before accbuf reuse is observed
        {
            int row = (w >> 2) * 16 + (lane >> 2);
            int col = 16 * (w & 3) + (lane & 3) * 2;
            accbuf[row * 66 + col]           = acc0[0];
            accbuf[row * 66 + col + 1]       = acc0[1];
            accbuf[(row + 8) * 66 + col]     = acc0[2];
            accbuf[(row + 8) * 66 + col + 1] = acc0[3];
            accbuf[row * 66 + col + 8]           = acc1[0];
            accbuf[row * 66 + col + 9]           = acc1[1];
            accbuf[(row + 8) * 66 + col + 8]     = acc1[2];
            accbuf[(row + 8) * 66 + col + 9]     = acc1[3];
        }
        __syncthreads();

        // ---- pointwise GRU update, fully local ----
        {
            float gr0 = accbuf[pj * 66 + pb],        gr1 = accbuf[(pj + 1) * 66 + pb];
            float gz0 = accbuf[(8 + pj) * 66 + pb],  gz1 = accbuf[(9 + pj) * 66 + pb];
            float gn0 = accbuf[(16 + pj) * 66 + pb], gn1 = accbuf[(17 + pj) * 66 + pb];

            float r0 = 1.f / (1.f + expf(-(xr.x + gr0 + br0)));
            float r1 = 1.f / (1.f + expf(-(xr.y + gr1 + br1)));
            float z0 = 1.f / (1.f + expf(-(xz.x + gz0 + bz0)));
            float z1 = 1.f / (1.f + expf(-(xz.y + gz1 + bz1)));
            float n0 = tanhf(xn.x + r0 * (gn0 + bn0));
            float n1 = tanhf(xn.y + r1 * (gn1 + bn1));
            hm0 = (1.f - z0) * n0 + z0 * hm0;
            hm1 = (1.f - z1) * n1 + z1 * hm1;

            __nv_bfloat16 a = __float2bfloat16(hm0), b = __float2bfloat16(hm1);
            __nv_bfloat16 cc = __float2bfloat16(hm0 - __bfloat162float(a));
            __nv_bfloat16 dd = __float2bfloat16(hm1 - __bfloat162float(b));
            uint32_t ph = (uint32_t)__bfloat16_as_ushort(a) | ((uint32_t)__bfloat16_as_ushort(b) << 16);
            uint32_t pl = (uint32_t)__bfloat16_as_ushort(cc) | ((uint32_t)__bfloat16_as_ushort(dd) << 16);
            __nv_bfloat16* dsth = (t & 1) ? hbh0 : hbh1;
            __nv_bfloat16* dstl = (t & 1) ? hbl0 : hbl1;
            *(uint32_t*)&dsth[(size_t)pb * HH + j0 + pj] = ph;
            *(uint32_t*)&dstl[(size_t)pb * HH + j0 + pj] = pl;
            *(float2*)&Y[((size_t)t * BB + pb) * HH + j0 + pj] = make_float2(hm0, hm1);
        }

        grid_bar();
    }

    if (hn != nullptr)
        *(float2*)&hn[(size_t)pb * HH + j0 + pj] = make_float2(hm0, hm1);
}

// ---------------- launch -------------------------------------------------------
extern "C" void kernel_launch(void* const* d_in, const int* in_sizes, int n_in,
                              void* d_out, int out_size)
{
    const float* x   = (const float*)d_in[0];
    const float* h0  = (const float*)d_in[1];
    const float* Wih = (const float*)d_in[2];
    const float* Whh = (const float*)d_in[3];
    const float* bih = (const float*)d_in[4];
    const float* bhh = (const float*)d_in[5];
    float* out = (float*)d_out;

    float *xg, *y1;
    __nv_bfloat16 *xhi, *xlo, *whi, *wlo, *vhi, *vlo, *hbh, *hbl;
    cudaGetSymbolAddress((void**)&xg,  g_xg);
    cudaGetSymbolAddress((void**)&y1,  g_y1);
    cudaGetSymbolAddress((void**)&xhi, g_xhi);
    cudaGetSymbolAddress((void**)&xlo, g_xlo);
    cudaGetSymbolAddress((void**)&whi, g_whi);
    cudaGetSymbolAddress((void**)&wlo, g_wlo);
    cudaGetSymbolAddress((void**)&vhi, g_vhi);
    cudaGetSymbolAddress((void**)&vlo, g_vlo);
    cudaGetSymbolAddress((void**)&hbh, g_hbh);
    cudaGetSymbolAddress((void**)&hbl, g_hbl);

    const int gemmSmem = 4 * 128 * SROW * 2;               // 73728 B
    static bool attr_set = false;
    if (!attr_set) {
        cudaFuncSetAttribute(gemm_xg_hmma,
                             cudaFuncAttributeMaxDynamicSharedMemorySize, gemmSmem);
        cudaFuncSetAttribute(gru_rec_v3,
                             cudaFuncAttributeMaxDynamicSharedMemorySize, REC_SMEM);
        attr_set = true;
    }

    const dim3 gemmGrid(G3 / 128, (TT * BB) / 128);        // 24 x 256
    const int  n4x = TT * BB * HH / 4;
    const int  n4w = G3 * HH / 4;
    const bool write_hn = (out_size >= TT * BB * HH + LL * BB * HH);

    bar_reset_kernel<<<1, 1>>>();

    for (int l = 0; l < LL; l++) {
        const float* Xin = (l == 0) ? x : y1;
        float* Y         = (l == 0) ? y1 : out;
        float* hn        = write_hn
            ? out + (size_t)TT * BB * HH + (size_t)l * BB * HH : nullptr;

        split_f32_kernel<<<(n4x + 255) / 256, 256>>>(Xin, xhi, xlo, n4x);
        split_f32_kernel<<<(n4w + 255) / 256, 256>>>(Wih + (size_t)l * G3 * HH,
                                                     whi, wlo, n4w);
        split_f32_kernel<<<(n4w + 255) / 256, 256>>>(Whh + (size_t)l * G3 * HH,
                                                     vhi, vlo, n4w);

        gemm_xg_hmma<<<gemmGrid, 256, gemmSmem>>>(xhi, xlo, whi, wlo,
                                                  bih + (size_t)l * G3, xg);

        gru_rec_v3<<<RB, 256, REC_SMEM>>>(h0 + (size_t)l * BB * HH,
                                          vhi, vlo, bhh + (size_t)l * G3,
                                          xg, Y, hn,
                                          hbh, hbl,
                                          hbh + BB * HH, hbl + BB * HH);
    }
}